// round 1
// baseline (speedup 1.0000x reference)
#include <cuda_runtime.h>
#include <math.h>

#define NN 100000
#define EE 1600000
#define FIN 100

// ---------------- scratch (static device allocations; no runtime mallocs) ----
__device__ float g_bufA[NN * 256];
__device__ float g_bufB[NN * 256];
__device__ int   g_deg[NN];
__device__ int   g_incl[NN];
__device__ int   g_rowptr[NN + 1];
__device__ int   g_cursor[NN];
__device__ int   g_col[EE];
__device__ float g_dinv[NN];
__device__ int   g_part[128];
__device__ float g_bnsum[256];   // [0:128) sum, [128:256) sumsq
__device__ float g_bncoef[256];  // [0:128) scale, [128:256) shift

// ---------------- CSR build ----------------
__global__ void k_zero() {
    int i = blockIdx.x * blockDim.x + threadIdx.x;
    if (i < NN) g_deg[i] = 0;
    if (i < 256) g_bnsum[i] = 0.0f;
}

__global__ void k_count(const int* __restrict__ dst) {
    int e = blockIdx.x * blockDim.x + threadIdx.x;
    if (e < EE) atomicAdd(&g_deg[dst[e]], 1);
}

__global__ void k_scan1() {  // block-level inclusive scan of g_deg
    __shared__ int sh[1024];
    int i = blockIdx.x * 1024 + threadIdx.x;
    int v = (i < NN) ? g_deg[i] : 0;
    sh[threadIdx.x] = v;
    __syncthreads();
    for (int off = 1; off < 1024; off <<= 1) {
        int t = (threadIdx.x >= (unsigned)off) ? sh[threadIdx.x - off] : 0;
        __syncthreads();
        sh[threadIdx.x] += t;
        __syncthreads();
    }
    if (i < NN) g_incl[i] = sh[threadIdx.x];
    if (threadIdx.x == 1023) g_part[blockIdx.x] = sh[1023];
}

__global__ void k_scan2(int nb) {  // exclusive scan of block partials (nb <= 128)
    __shared__ int sh[128];
    int t = threadIdx.x;
    sh[t] = (t < nb) ? g_part[t] : 0;
    __syncthreads();
    for (int off = 1; off < 128; off <<= 1) {
        int u = (t >= off) ? sh[t - off] : 0;
        __syncthreads();
        sh[t] += u;
        __syncthreads();
    }
    g_part[t] = (t == 0) ? 0 : sh[t - 1];
}

__global__ void k_rowptr() {
    int i = blockIdx.x * blockDim.x + threadIdx.x;
    if (i >= NN) return;
    int excl = g_incl[i] - g_deg[i] + g_part[i >> 10];
    g_rowptr[i] = excl;
    g_cursor[i] = excl;
    g_dinv[i] = rsqrtf((float)g_deg[i] + 1.0f);
    if (i == NN - 1) g_rowptr[NN] = g_incl[i] + g_part[i >> 10];
}

__global__ void k_fill(const int* __restrict__ src, const int* __restrict__ dst) {
    int e = blockIdx.x * blockDim.x + threadIdx.x;
    if (e >= EE) return;
    int p = atomicAdd(&g_cursor[dst[e]], 1);
    g_col[p] = src[e];
}

// ---------------- aggregation: out = Ahat * in  (width 100), warp per node ---
__global__ void k_agg(const float* __restrict__ in, float* __restrict__ out, int clip) {
    int gw = (blockIdx.x * blockDim.x + threadIdx.x) >> 5;
    if (gw >= NN) return;
    int lane = threadIdx.x & 31;
    bool f3 = lane < 4;
    float di = g_dinv[gw];
    int s0 = g_rowptr[gw], s1 = g_rowptr[gw + 1];
    float a0 = 0.f, a1 = 0.f, a2 = 0.f, a3 = 0.f;
    for (int e = s0; e < s1; e++) {
        int s = __ldg(&g_col[e]);
        float nr = __ldg(&g_dinv[s]) * di;
        const float* r = in + s * FIN;
        float v0 = __ldg(&r[lane]);
        float v1 = __ldg(&r[lane + 32]);
        float v2 = __ldg(&r[lane + 64]);
        float v3 = f3 ? __ldg(&r[lane + 96]) : 0.f;
        if (clip) {
            v0 = fminf(fmaxf(v0, -0.4f), 0.4f);
            v1 = fminf(fmaxf(v1, -0.4f), 0.4f);
            v2 = fminf(fmaxf(v2, -0.4f), 0.4f);
            v3 = fminf(fmaxf(v3, -0.4f), 0.4f);
        }
        a0 += nr * v0; a1 += nr * v1; a2 += nr * v2; a3 += nr * v3;
    }
    {   // self loop
        float nn = di * di;
        const float* r = in + gw * FIN;
        float v0 = r[lane], v1 = r[lane + 32], v2 = r[lane + 64];
        float v3 = f3 ? r[lane + 96] : 0.f;
        if (clip) {
            v0 = fminf(fmaxf(v0, -0.4f), 0.4f);
            v1 = fminf(fmaxf(v1, -0.4f), 0.4f);
            v2 = fminf(fmaxf(v2, -0.4f), 0.4f);
            v3 = fminf(fmaxf(v3, -0.4f), 0.4f);
        }
        a0 += nn * v0; a1 += nn * v1; a2 += nn * v2; a3 += nn * v3;
    }
    float* o = out + gw * FIN;
    o[lane] = a0; o[lane + 32] = a1; o[lane + 64] = a2;
    if (f3) o[lane + 96] = a3;
}

// ---------------- tiled fp32 GEMM: C[NN,Nc] = act(A[NN,K] @ B[K,Nc] + bias) --
__global__ void k_gemm(const float* __restrict__ A, const float* __restrict__ B,
                       const float* __restrict__ bias, float* __restrict__ C,
                       int K, int Nc, int relu) {
    __shared__ float As[16][68];
    __shared__ float Bs[16][68];
    int tid = threadIdx.x;                 // 256 threads
    int tm = (tid >> 4) << 2;              // 0..60
    int tn = (tid & 15) << 2;              // 0..60
    int br = blockIdx.y << 6, bc = blockIdx.x << 6;
    float acc[4][4] = {};
    for (int k0 = 0; k0 < K; k0 += 16) {
        #pragma unroll
        for (int i = tid; i < 1024; i += 256) {
            int m = i >> 4, k = i & 15;
            int gm = br + m, gk = k0 + k;
            As[k][m] = (gm < NN && gk < K) ? A[gm * K + gk] : 0.f;
        }
        #pragma unroll
        for (int i = tid; i < 1024; i += 256) {
            int k = i >> 6, n = i & 63;
            int gk = k0 + k, gn = bc + n;
            Bs[k][n] = (gk < K && gn < Nc) ? B[gk * Nc + gn] : 0.f;
        }
        __syncthreads();
        #pragma unroll
        for (int k = 0; k < 16; k++) {
            float4 av = *(const float4*)&As[k][tm];
            float4 bv = *(const float4*)&Bs[k][tn];
            float a[4] = {av.x, av.y, av.z, av.w};
            float b[4] = {bv.x, bv.y, bv.z, bv.w};
            #pragma unroll
            for (int i = 0; i < 4; i++)
                #pragma unroll
                for (int j = 0; j < 4; j++)
                    acc[i][j] += a[i] * b[j];
        }
        __syncthreads();
    }
    #pragma unroll
    for (int i = 0; i < 4; i++) {
        int gm = br + tm + i;
        if (gm >= NN) continue;
        #pragma unroll
        for (int j = 0; j < 4; j++) {
            int gn = bc + tn + j;
            if (gn < Nc) {
                float v = acc[i][j] + bias[gn];
                if (relu) v = fmaxf(v, 0.f);
                C[gm * Nc + gn] = v;
            }
        }
    }
}

// ---------------- BatchNorm statistics over z[NN,128] -----------------------
__global__ void k_bnstat(const float* __restrict__ z) {
    int col = threadIdx.x & 127;
    int half = threadIdx.x >> 7;
    float s = 0.f, s2 = 0.f;
    for (int r = blockIdx.x * 2 + half; r < NN; r += gridDim.x * 2) {
        float v = z[r * 128 + col];
        s += v; s2 += v * v;
    }
    __shared__ float sh[256], sh2[256];
    sh[threadIdx.x] = s; sh2[threadIdx.x] = s2;
    __syncthreads();
    if (threadIdx.x < 128) {
        atomicAdd(&g_bnsum[col], sh[threadIdx.x] + sh[threadIdx.x + 128]);
        atomicAdd(&g_bnsum[128 + col], sh2[threadIdx.x] + sh2[threadIdx.x + 128]);
    }
}

__global__ void k_bncoef(const float* __restrict__ gamma, const float* __restrict__ beta) {
    int c = threadIdx.x;  // 128
    float inv = 1.0f / (float)NN;
    float mu = g_bnsum[c] * inv;
    float var = g_bnsum[128 + c] * inv - mu * mu;
    float sc = gamma[c] * rsqrtf(var + 1e-5f);
    g_bncoef[c] = sc;
    g_bncoef[128 + c] = beta[c] - mu * sc;
}

// ------- final: BN affine + ReLU + [128x19] GEMV + log_softmax, warp/row ----
__global__ void k_final_out(const float* __restrict__ z, const float* __restrict__ W,
                            const float* __restrict__ b, float* __restrict__ out) {
    int gw = (blockIdx.x * blockDim.x + threadIdx.x) >> 5;
    if (gw >= NN) return;
    int lane = threadIdx.x & 31;
    float h[4];
    #pragma unroll
    for (int u = 0; u < 4; u++) {
        int c = lane + 32 * u;
        float v = z[gw * 128 + c];
        h[u] = fmaxf(v * g_bncoef[c] + g_bncoef[128 + c], 0.f);
    }
    float acc = (lane < 19) ? b[lane] : 0.f;
    #pragma unroll
    for (int u = 0; u < 4; u++) {
        #pragma unroll
        for (int l = 0; l < 32; l++) {
            float hb = __shfl_sync(0xffffffffu, h[u], l);
            if (lane < 19) acc += hb * __ldg(&W[(u * 32 + l) * 19 + lane]);
        }
    }
    float v = (lane < 19) ? acc : -3.4e38f;
    float m = v;
    #pragma unroll
    for (int off = 16; off > 0; off >>= 1) m = fmaxf(m, __shfl_xor_sync(0xffffffffu, m, off));
    float ex = (lane < 19) ? expf(v - m) : 0.f;
    float ssum = ex;
    #pragma unroll
    for (int off = 16; off > 0; off >>= 1) ssum += __shfl_xor_sync(0xffffffffu, ssum, off);
    if (lane < 19) out[gw * 19 + lane] = v - m - logf(ssum);
}

// ---------------------------------------------------------------------------
extern "C" void kernel_launch(void* const* d_in, const int* in_sizes, int n_in,
                              void* d_out, int out_size) {
    const float* x     = (const float*)d_in[0];
    const int*   ei    = (const int*)d_in[1];
    const float* W1    = (const float*)d_in[2];
    const float* b1    = (const float*)d_in[3];
    const float* W2    = (const float*)d_in[4];
    const float* b2    = (const float*)d_in[5];
    const float* W3    = (const float*)d_in[6];
    const float* b3    = (const float*)d_in[7];
    const float* fc1W  = (const float*)d_in[8];
    const float* fc1b  = (const float*)d_in[9];
    const float* fc2aW = (const float*)d_in[10];
    const float* fc2ab = (const float*)d_in[11];
    const float* gamma = (const float*)d_in[12];
    const float* beta  = (const float*)d_in[13];
    const float* fc2bW = (const float*)d_in[14];
    const float* fc2bb = (const float*)d_in[15];
    float* out = (float*)d_out;

    const int* src = ei;        // edge_index[0]
    const int* dst = ei + EE;   // edge_index[1]

    float *bufA, *bufB;
    cudaGetSymbolAddress((void**)&bufA, g_bufA);
    cudaGetSymbolAddress((void**)&bufB, g_bufB);

    // CSR build (every launch; deterministic)
    k_zero<<<(NN + 255) / 256, 256>>>();
    k_count<<<(EE + 255) / 256, 256>>>(dst);
    k_scan1<<<(NN + 1023) / 1024, 1024>>>();
    k_scan2<<<1, 128>>>((NN + 1023) / 1024);
    k_rowptr<<<(NN + 255) / 256, 256>>>();
    k_fill<<<(EE + 255) / 256, 256>>>(src, dst);

    const int aggBlocks = (NN * 32 + 255) / 256;
    dim3 g100(2, (NN + 63) / 64);
    dim3 g256(4, (NN + 63) / 64);
    dim3 g128(2, (NN + 63) / 64);

    // conv1: a = Ahat clip(x); h = relu(a W1 + b1)
    k_agg<<<aggBlocks, 256>>>(x, bufB, 1);
    k_gemm<<<g100, 256>>>(bufB, W1, b1, bufA, FIN, FIN, 1);
    // conv2
    k_agg<<<aggBlocks, 256>>>(bufA, bufB, 0);
    k_gemm<<<g100, 256>>>(bufB, W2, b2, bufA, FIN, FIN, 1);
    // conv3 (aggregate at width 100, then widen to 256)
    k_agg<<<aggBlocks, 256>>>(bufA, bufB, 0);
    k_gemm<<<g256, 256>>>(bufB, W3, b3, bufA, FIN, 256, 1);
    // fc1
    k_gemm<<<g256, 256>>>(bufA, fc1W, fc1b, bufB, 256, 256, 1);
    // fc2a (no relu; BN comes next)
    k_gemm<<<g128, 256>>>(bufB, fc2aW, fc2ab, bufA, 256, 128, 0);
    // BN stats + coefficients
    k_bnstat<<<512, 256>>>(bufA);
    k_bncoef<<<1, 128>>>(gamma, beta);
    // BN + ReLU + final linear + log_softmax
    k_final_out<<<aggBlocks, 256>>>(bufA, fc2bW, fc2bb, out);
}

// round 2
// speedup vs baseline: 1.5315x; 1.5315x over previous
#include <cuda_runtime.h>
#include <math.h>

#define NN 100000
#define EE 1600000
#define FIN 100

typedef unsigned long long ull;

// ---------------- scratch (static device allocations; no runtime mallocs) ----
__device__ float g_bufA[NN * 256];
__device__ float g_bufB[NN * 256];
__device__ int   g_deg[NN];
__device__ int   g_incl[NN];
__device__ int   g_rowptr[NN + 1];
__device__ int   g_cursor[NN];
__device__ int   g_col[EE];
__device__ float g_dinv[NN];
__device__ int   g_part[128];
__device__ float g_bnsum[256];   // [0:128) sum, [128:256) sumsq
__device__ float g_bncoef[256];  // [0:128) scale, [128:256) shift

// ---------------- CSR build ----------------
__global__ void k_zero() {
    int i = blockIdx.x * blockDim.x + threadIdx.x;
    if (i < NN) g_deg[i] = 0;
    if (i < 256) g_bnsum[i] = 0.0f;
}

__global__ void k_count(const int* __restrict__ dst) {
    int e = blockIdx.x * blockDim.x + threadIdx.x;
    if (e < EE) atomicAdd(&g_deg[dst[e]], 1);
}

__global__ void k_scan1() {  // block-level inclusive scan of g_deg
    __shared__ int sh[1024];
    int i = blockIdx.x * 1024 + threadIdx.x;
    int v = (i < NN) ? g_deg[i] : 0;
    sh[threadIdx.x] = v;
    __syncthreads();
    for (int off = 1; off < 1024; off <<= 1) {
        int t = (threadIdx.x >= (unsigned)off) ? sh[threadIdx.x - off] : 0;
        __syncthreads();
        sh[threadIdx.x] += t;
        __syncthreads();
    }
    if (i < NN) g_incl[i] = sh[threadIdx.x];
    if (threadIdx.x == 1023) g_part[blockIdx.x] = sh[1023];
}

__global__ void k_scan2(int nb) {  // exclusive scan of block partials (nb <= 128)
    __shared__ int sh[128];
    int t = threadIdx.x;
    sh[t] = (t < nb) ? g_part[t] : 0;
    __syncthreads();
    for (int off = 1; off < 128; off <<= 1) {
        int u = (t >= off) ? sh[t - off] : 0;
        __syncthreads();
        sh[t] += u;
        __syncthreads();
    }
    g_part[t] = (t == 0) ? 0 : sh[t - 1];
}

__global__ void k_rowptr() {
    int i = blockIdx.x * blockDim.x + threadIdx.x;
    if (i >= NN) return;
    int excl = g_incl[i] - g_deg[i] + g_part[i >> 10];
    g_rowptr[i] = excl;
    g_cursor[i] = excl;
    g_dinv[i] = rsqrtf((float)g_deg[i] + 1.0f);
    if (i == NN - 1) g_rowptr[NN] = g_incl[i] + g_part[i >> 10];
}

__global__ void k_fill(const int* __restrict__ src, const int* __restrict__ dst) {
    int e = blockIdx.x * blockDim.x + threadIdx.x;
    if (e >= EE) return;
    int p = atomicAdd(&g_cursor[dst[e]], 1);
    g_col[p] = src[e];
}

// ---------------- aggregation: out = Ahat * in  (width 100), warp per node ---
__global__ void k_agg(const float* __restrict__ in, float* __restrict__ out, int clip) {
    int gw = (blockIdx.x * blockDim.x + threadIdx.x) >> 5;
    if (gw >= NN) return;
    int lane = threadIdx.x & 31;
    bool f3 = lane < 4;
    float di = g_dinv[gw];
    int s0 = g_rowptr[gw], s1 = g_rowptr[gw + 1];
    float a0 = 0.f, a1 = 0.f, a2 = 0.f, a3 = 0.f;
    for (int e = s0; e < s1; e++) {
        int s = __ldg(&g_col[e]);
        float nr = __ldg(&g_dinv[s]) * di;
        const float* r = in + s * FIN;
        float v0 = __ldg(&r[lane]);
        float v1 = __ldg(&r[lane + 32]);
        float v2 = __ldg(&r[lane + 64]);
        float v3 = f3 ? __ldg(&r[lane + 96]) : 0.f;
        if (clip) {
            v0 = fminf(fmaxf(v0, -0.4f), 0.4f);
            v1 = fminf(fmaxf(v1, -0.4f), 0.4f);
            v2 = fminf(fmaxf(v2, -0.4f), 0.4f);
            v3 = fminf(fmaxf(v3, -0.4f), 0.4f);
        }
        a0 += nr * v0; a1 += nr * v1; a2 += nr * v2; a3 += nr * v3;
    }
    {   // self loop
        float nn = di * di;
        const float* r = in + gw * FIN;
        float v0 = r[lane], v1 = r[lane + 32], v2 = r[lane + 64];
        float v3 = f3 ? r[lane + 96] : 0.f;
        if (clip) {
            v0 = fminf(fmaxf(v0, -0.4f), 0.4f);
            v1 = fminf(fmaxf(v1, -0.4f), 0.4f);
            v2 = fminf(fmaxf(v2, -0.4f), 0.4f);
            v3 = fminf(fmaxf(v3, -0.4f), 0.4f);
        }
        a0 += nn * v0; a1 += nn * v1; a2 += nn * v2; a3 += nn * v3;
    }
    float* o = out + gw * FIN;
    o[lane] = a0; o[lane + 32] = a1; o[lane + 64] = a2;
    if (f3) o[lane + 96] = a3;
}

// ---------------- packed f32x2 helpers ----------------
__device__ __forceinline__ ull dup2(float a) {
    ull r;
    asm("mov.b64 %0, {%1, %1};" : "=l"(r) : "f"(a));
    return r;
}
__device__ __forceinline__ void ffma2(ull& c, ull a, ull b) {
    asm("fma.rn.f32x2 %0, %1, %2, %3;" : "=l"(c) : "l"(a), "l"(b), "l"(c));
}

// ------- 128x128x16 tiled fp32 GEMM with FFMA2 (f32x2), double-buffered -----
// C[M,Nc] = act(A[M,K] @ B[K,Nc] + bias)
#define BM 128
#define BN 128
#define BK 16
#define BNP 132  // padded row for Bs

__global__ void __launch_bounds__(256, 2)
k_gemm2(const float* __restrict__ A, const float* __restrict__ B,
        const float* __restrict__ bias, float* __restrict__ C,
        int M, int K, int Nc, int relu) {
    __shared__ float As[2][BK][BM];
    __shared__ float Bs[2][BK][BNP];

    int tid = threadIdx.x;
    int br = blockIdx.y * BM, bc = blockIdx.x * BN;

    // A staging: thread loads rows ar, ar+64; 4 k-cols at ak
    int ar = tid >> 2;
    int ak = (tid & 3) << 2;
    // B staging: thread loads k-rows bk, bk+8; 4 n-cols at bn
    int bk = tid >> 5;
    int bn = (tid & 31) << 2;
    // compute fragment origin
    int ra = (tid >> 4) << 2;   // rows ra..ra+3, ra+64..ra+67
    int cb = (tid & 15) << 2;   // cols cb..cb+3, cb+64..cb+67

    float a_pf[8];  // prefetch regs: (ar,k0+ak..+3), (ar+64, ...)
    float b_pf[8];  // (bk, bc+bn..+3), (bk+8, ...)

    int nt = (K + BK - 1) / BK;

    // ---- load tile 0 into regs ----
    {
        int k0 = 0;
        #pragma unroll
        for (int h = 0; h < 2; h++) {
            int gm = br + ar + h * 64;
            #pragma unroll
            for (int j = 0; j < 4; j++) {
                int gk = k0 + ak + j;
                a_pf[h * 4 + j] = (gm < M && gk < K) ? __ldg(&A[(size_t)gm * K + gk]) : 0.f;
            }
        }
        #pragma unroll
        for (int h = 0; h < 2; h++) {
            int gk = k0 + bk + h * 8;
            #pragma unroll
            for (int j = 0; j < 4; j++) {
                int gn = bc + bn + j;
                b_pf[h * 4 + j] = (gk < K && gn < Nc) ? __ldg(&B[(size_t)gk * Nc + gn]) : 0.f;
            }
        }
    }
    // store to smem buf 0
    #pragma unroll
    for (int h = 0; h < 2; h++)
        #pragma unroll
        for (int j = 0; j < 4; j++)
            As[0][ak + j][ar + h * 64] = a_pf[h * 4 + j];
    #pragma unroll
    for (int h = 0; h < 2; h++)
        #pragma unroll
        for (int j = 0; j < 4; j++)
            Bs[0][bk + h * 8][bn + j] = b_pf[h * 4 + j];
    __syncthreads();

    ull acc[8][4];
    #pragma unroll
    for (int i = 0; i < 8; i++)
        #pragma unroll
        for (int p = 0; p < 4; p++) acc[i][p] = 0ull;

    for (int t = 0; t < nt; t++) {
        int buf = t & 1;
        // prefetch next tile
        if (t + 1 < nt) {
            int k0 = (t + 1) * BK;
            #pragma unroll
            for (int h = 0; h < 2; h++) {
                int gm = br + ar + h * 64;
                #pragma unroll
                for (int j = 0; j < 4; j++) {
                    int gk = k0 + ak + j;
                    a_pf[h * 4 + j] = (gm < M && gk < K) ? __ldg(&A[(size_t)gm * K + gk]) : 0.f;
                }
            }
            #pragma unroll
            for (int h = 0; h < 2; h++) {
                int gk = k0 + bk + h * 8;
                #pragma unroll
                for (int j = 0; j < 4; j++) {
                    int gn = bc + bn + j;
                    b_pf[h * 4 + j] = (gk < K && gn < Nc) ? __ldg(&B[(size_t)gk * Nc + gn]) : 0.f;
                }
            }
        }
        // compute on current buffer
        #pragma unroll
        for (int k = 0; k < BK; k++) {
            float4 a0 = *(const float4*)&As[buf][k][ra];
            float4 a1 = *(const float4*)&As[buf][k][ra + 64];
            ull b0 = *(const ull*)&Bs[buf][k][cb];
            ull b1 = *(const ull*)&Bs[buf][k][cb + 2];
            ull b2 = *(const ull*)&Bs[buf][k][cb + 64];
            ull b3 = *(const ull*)&Bs[buf][k][cb + 66];
            ull ad[8];
            ad[0] = dup2(a0.x); ad[1] = dup2(a0.y); ad[2] = dup2(a0.z); ad[3] = dup2(a0.w);
            ad[4] = dup2(a1.x); ad[5] = dup2(a1.y); ad[6] = dup2(a1.z); ad[7] = dup2(a1.w);
            #pragma unroll
            for (int i = 0; i < 8; i++) {
                ffma2(acc[i][0], ad[i], b0);
                ffma2(acc[i][1], ad[i], b1);
                ffma2(acc[i][2], ad[i], b2);
                ffma2(acc[i][3], ad[i], b3);
            }
        }
        // stage next tile into the other buffer
        if (t + 1 < nt) {
            int nb = buf ^ 1;
            #pragma unroll
            for (int h = 0; h < 2; h++)
                #pragma unroll
                for (int j = 0; j < 4; j++)
                    As[nb][ak + j][ar + h * 64] = a_pf[h * 4 + j];
            #pragma unroll
            for (int h = 0; h < 2; h++)
                #pragma unroll
                for (int j = 0; j < 4; j++)
                    Bs[nb][bk + h * 8][bn + j] = b_pf[h * 4 + j];
        }
        __syncthreads();
    }

    // ---- epilogue ----
    #pragma unroll
    for (int i = 0; i < 8; i++) {
        int gm = br + ra + (i & 3) + ((i >= 4) ? 64 : 0);
        if (gm >= M) continue;
        #pragma unroll
        for (int p = 0; p < 4; p++) {
            int gn = bc + cb + ((p & 1) ? 2 : 0) + ((p >= 2) ? 64 : 0);
            float2 f = *reinterpret_cast<float2*>(&acc[i][p]);
            if (gn < Nc) {
                float v = f.x + bias[gn];
                if (relu) v = fmaxf(v, 0.f);
                C[(size_t)gm * Nc + gn] = v;
            }
            if (gn + 1 < Nc) {
                float v = f.y + bias[gn + 1];
                if (relu) v = fmaxf(v, 0.f);
                C[(size_t)gm * Nc + gn + 1] = v;
            }
        }
    }
}

// ---------------- BatchNorm statistics over z[NN,128] -----------------------
__global__ void k_bnstat(const float* __restrict__ z) {
    int col = threadIdx.x & 127;
    int half = threadIdx.x >> 7;
    float s = 0.f, s2 = 0.f;
    for (int r = blockIdx.x * 2 + half; r < NN; r += gridDim.x * 2) {
        float v = z[r * 128 + col];
        s += v; s2 += v * v;
    }
    __shared__ float sh[256], sh2[256];
    sh[threadIdx.x] = s; sh2[threadIdx.x] = s2;
    __syncthreads();
    if (threadIdx.x < 128) {
        atomicAdd(&g_bnsum[col], sh[threadIdx.x] + sh[threadIdx.x + 128]);
        atomicAdd(&g_bnsum[128 + col], sh2[threadIdx.x] + sh2[threadIdx.x + 128]);
    }
}

__global__ void k_bncoef(const float* __restrict__ gamma, const float* __restrict__ beta) {
    int c = threadIdx.x;  // 128
    float inv = 1.0f / (float)NN;
    float mu = g_bnsum[c] * inv;
    float var = g_bnsum[128 + c] * inv - mu * mu;
    float sc = gamma[c] * rsqrtf(var + 1e-5f);
    g_bncoef[c] = sc;
    g_bncoef[128 + c] = beta[c] - mu * sc;
}

// ------- final: BN affine + ReLU + [128x19] GEMV + log_softmax, warp/row ----
__global__ void k_final_out(const float* __restrict__ z, const float* __restrict__ W,
                            const float* __restrict__ b, float* __restrict__ out) {
    int gw = (blockIdx.x * blockDim.x + threadIdx.x) >> 5;
    if (gw >= NN) return;
    int lane = threadIdx.x & 31;
    float h[4];
    #pragma unroll
    for (int u = 0; u < 4; u++) {
        int c = lane + 32 * u;
        float v = z[gw * 128 + c];
        h[u] = fmaxf(v * g_bncoef[c] + g_bncoef[128 + c], 0.f);
    }
    float acc = (lane < 19) ? b[lane] : 0.f;
    #pragma unroll
    for (int u = 0; u < 4; u++) {
        #pragma unroll
        for (int l = 0; l < 32; l++) {
            float hb = __shfl_sync(0xffffffffu, h[u], l);
            if (lane < 19) acc += hb * __ldg(&W[(u * 32 + l) * 19 + lane]);
        }
    }
    float v = (lane < 19) ? acc : -3.4e38f;
    float m = v;
    #pragma unroll
    for (int off = 16; off > 0; off >>= 1) m = fmaxf(m, __shfl_xor_sync(0xffffffffu, m, off));
    float ex = (lane < 19) ? expf(v - m) : 0.f;
    float ssum = ex;
    #pragma unroll
    for (int off = 16; off > 0; off >>= 1) ssum += __shfl_xor_sync(0xffffffffu, ssum, off);
    if (lane < 19) out[gw * 19 + lane] = v - m - logf(ssum);
}

// ---------------------------------------------------------------------------
extern "C" void kernel_launch(void* const* d_in, const int* in_sizes, int n_in,
                              void* d_out, int out_size) {
    const float* x     = (const float*)d_in[0];
    const int*   ei    = (const int*)d_in[1];
    const float* W1    = (const float*)d_in[2];
    const float* b1    = (const float*)d_in[3];
    const float* W2    = (const float*)d_in[4];
    const float* b2    = (const float*)d_in[5];
    const float* W3    = (const float*)d_in[6];
    const float* b3    = (const float*)d_in[7];
    const float* fc1W  = (const float*)d_in[8];
    const float* fc1b  = (const float*)d_in[9];
    const float* fc2aW = (const float*)d_in[10];
    const float* fc2ab = (const float*)d_in[11];
    const float* gamma = (const float*)d_in[12];
    const float* beta  = (const float*)d_in[13];
    const float* fc2bW = (const float*)d_in[14];
    const float* fc2bb = (const float*)d_in[15];
    float* out = (float*)d_out;

    const int* src = ei;        // edge_index[0]
    const int* dst = ei + EE;   // edge_index[1]

    float *bufA, *bufB;
    cudaGetSymbolAddress((void**)&bufA, g_bufA);
    cudaGetSymbolAddress((void**)&bufB, g_bufB);

    // CSR build (every launch; deterministic)
    k_zero<<<(NN + 255) / 256, 256>>>();
    k_count<<<(EE + 255) / 256, 256>>>(dst);
    k_scan1<<<(NN + 1023) / 1024, 1024>>>();
    k_scan2<<<1, 128>>>((NN + 1023) / 1024);
    k_rowptr<<<(NN + 255) / 256, 256>>>();
    k_fill<<<(EE + 255) / 256, 256>>>(src, dst);

    const int aggBlocks = (NN * 32 + 255) / 256;
    const int gy = (NN + BM - 1) / BM;  // 782
    dim3 g100(1, gy);
    dim3 g256(2, gy);
    dim3 g128(1, gy);

    // conv1: a = Ahat clip(x); h = relu(a W1 + b1)
    k_agg<<<aggBlocks, 256>>>(x, bufB, 1);
    k_gemm2<<<g100, 256>>>(bufB, W1, b1, bufA, NN, FIN, FIN, 1);
    // conv2
    k_agg<<<aggBlocks, 256>>>(bufA, bufB, 0);
    k_gemm2<<<g100, 256>>>(bufB, W2, b2, bufA, NN, FIN, FIN, 1);
    // conv3 (aggregate at width 100, then widen to 256)
    k_agg<<<aggBlocks, 256>>>(bufA, bufB, 0);
    k_gemm2<<<g256, 256>>>(bufB, W3, b3, bufA, NN, FIN, 256, 1);
    // fc1
    k_gemm2<<<g256, 256>>>(bufA, fc1W, fc1b, bufB, NN, 256, 256, 1);
    // fc2a (no relu; BN comes next)
    k_gemm2<<<g128, 256>>>(bufB, fc2aW, fc2ab, bufA, NN, 256, 128, 0);
    // BN stats + coefficients
    k_bnstat<<<512, 256>>>(bufA);
    k_bncoef<<<1, 128>>>(gamma, beta);
    // BN + ReLU + final linear + log_softmax
    k_final_out<<<aggBlocks, 256>>>(bufA, fc2bW, fc2bb, out);
}

// round 4
// speedup vs baseline: 1.6634x; 1.0861x over previous
#include <cuda_runtime.h>
#include <cuda_bf16.h>
#include <math.h>
#include <stdint.h>

#define NN 100000
#define EE 1600000
#define FIN 100

typedef unsigned long long ull;

// ---------------- scratch (static device allocations; no runtime mallocs) ----
__device__ float g_bufA[NN * 256];
__device__ float g_bufB[NN * 256];
__device__ int   g_deg[NN];
__device__ int   g_incl[NN];
__device__ int   g_rowptr[NN + 1];
__device__ int   g_cursor[NN];
__device__ int   g_col[EE];
__device__ float g_dinv[NN];
__device__ int   g_part[128];
__device__ float g_bnsum[256];
__device__ float g_bncoef[256];
// transposed + split weights (bf16), [Npad][Kpad]
__device__ __align__(16) __nv_bfloat16 g_w1h[128 * 128], g_w1l[128 * 128];
__device__ __align__(16) __nv_bfloat16 g_w2h[128 * 128], g_w2l[128 * 128];
__device__ __align__(16) __nv_bfloat16 g_w3h[256 * 128], g_w3l[256 * 128];
__device__ __align__(16) __nv_bfloat16 g_f1h[256 * 256], g_f1l[256 * 256];
__device__ __align__(16) __nv_bfloat16 g_f2h[128 * 256], g_f2l[128 * 256];

// ---------------- PTX helpers ----------------
__device__ __forceinline__ uint32_t smem_u32(const void* p) {
    uint32_t a;
    asm("{ .reg .u64 t; cvta.to.shared.u64 t, %1; cvt.u32.u64 %0, t; }" : "=r"(a) : "l"(p));
    return a;
}
__device__ __forceinline__ void ldsm4(uint32_t addr, uint32_t* r) {
    asm volatile("ldmatrix.sync.aligned.m8n8.x4.shared.b16 {%0,%1,%2,%3}, [%4];"
                 : "=r"(r[0]), "=r"(r[1]), "=r"(r[2]), "=r"(r[3]) : "r"(addr));
}
__device__ __forceinline__ void mma16816(float* d, const uint32_t* a, const uint32_t* b) {
    asm volatile(
        "mma.sync.aligned.m16n8k16.row.col.f32.bf16.bf16.f32 "
        "{%0,%1,%2,%3}, {%4,%5,%6,%7}, {%8,%9}, {%0,%1,%2,%3};"
        : "+f"(d[0]), "+f"(d[1]), "+f"(d[2]), "+f"(d[3])
        : "r"(a[0]), "r"(a[1]), "r"(a[2]), "r"(a[3]), "r"(b[0]), "r"(b[1]));
}

// ---------------- CSR build ----------------
__global__ void k_zero() {
    int i = blockIdx.x * blockDim.x + threadIdx.x;
    if (i < NN) g_deg[i] = 0;
    if (i < 256) g_bnsum[i] = 0.0f;
}
__global__ void k_count(const int* __restrict__ dst) {
    int e = blockIdx.x * blockDim.x + threadIdx.x;
    if (e < EE) atomicAdd(&g_deg[dst[e]], 1);
}
__global__ void k_scan1() {
    __shared__ int sh[1024];
    int i = blockIdx.x * 1024 + threadIdx.x;
    int v = (i < NN) ? g_deg[i] : 0;
    sh[threadIdx.x] = v;
    __syncthreads();
    for (int off = 1; off < 1024; off <<= 1) {
        int t = (threadIdx.x >= (unsigned)off) ? sh[threadIdx.x - off] : 0;
        __syncthreads();
        sh[threadIdx.x] += t;
        __syncthreads();
    }
    if (i < NN) g_incl[i] = sh[threadIdx.x];
    if (threadIdx.x == 1023) g_part[blockIdx.x] = sh[1023];
}
__global__ void k_scan2(int nb) {
    __shared__ int sh[128];
    int t = threadIdx.x;
    sh[t] = (t < nb) ? g_part[t] : 0;
    __syncthreads();
    for (int off = 1; off < 128; off <<= 1) {
        int u = (t >= off) ? sh[t - off] : 0;
        __syncthreads();
        sh[t] += u;
        __syncthreads();
    }
    g_part[t] = (t == 0) ? 0 : sh[t - 1];
}
__global__ void k_rowptr() {
    int i = blockIdx.x * blockDim.x + threadIdx.x;
    if (i >= NN) return;
    int excl = g_incl[i] - g_deg[i] + g_part[i >> 10];
    g_rowptr[i] = excl;
    g_cursor[i] = excl;
    g_dinv[i] = rsqrtf((float)g_deg[i] + 1.0f);
    if (i == NN - 1) g_rowptr[NN] = g_incl[i] + g_part[i >> 10];
}
__global__ void k_fill(const int* __restrict__ src, const int* __restrict__ dst) {
    int e = blockIdx.x * blockDim.x + threadIdx.x;
    if (e >= EE) return;
    int p = atomicAdd(&g_cursor[dst[e]], 1);
    g_col[p] = src[e];
}

// ---------------- aggregation: out = Ahat * in  (width 100) ----------------
__global__ void k_agg(const float* __restrict__ in, float* __restrict__ out, int clip) {
    int gw = (blockIdx.x * blockDim.x + threadIdx.x) >> 5;
    if (gw >= NN) return;
    int lane = threadIdx.x & 31;
    bool f3 = lane < 4;
    float di = g_dinv[gw];
    int s0 = g_rowptr[gw], s1 = g_rowptr[gw + 1];
    float a0 = 0.f, a1 = 0.f, a2 = 0.f, a3 = 0.f;
    for (int e = s0; e < s1; e++) {
        int s = __ldg(&g_col[e]);
        float nr = __ldg(&g_dinv[s]) * di;
        const float* r = in + s * FIN;
        float v0 = __ldg(&r[lane]);
        float v1 = __ldg(&r[lane + 32]);
        float v2 = __ldg(&r[lane + 64]);
        float v3 = f3 ? __ldg(&r[lane + 96]) : 0.f;
        if (clip) {
            v0 = fminf(fmaxf(v0, -0.4f), 0.4f);
            v1 = fminf(fmaxf(v1, -0.4f), 0.4f);
            v2 = fminf(fmaxf(v2, -0.4f), 0.4f);
            v3 = fminf(fmaxf(v3, -0.4f), 0.4f);
        }
        a0 += nr * v0; a1 += nr * v1; a2 += nr * v2; a3 += nr * v3;
    }
    {
        float nn = di * di;
        const float* r = in + gw * FIN;
        float v0 = r[lane], v1 = r[lane + 32], v2 = r[lane + 64];
        float v3 = f3 ? r[lane + 96] : 0.f;
        if (clip) {
            v0 = fminf(fmaxf(v0, -0.4f), 0.4f);
            v1 = fminf(fmaxf(v1, -0.4f), 0.4f);
            v2 = fminf(fmaxf(v2, -0.4f), 0.4f);
            v3 = fminf(fmaxf(v3, -0.4f), 0.4f);
        }
        a0 += nn * v0; a1 += nn * v1; a2 += nn * v2; a3 += nn * v3;
    }
    float* o = out + gw * FIN;
    o[lane] = a0; o[lane + 32] = a1; o[lane + 64] = a2;
    if (f3) o[lane + 96] = a3;
}

// ------- weight prep: Wt_hi/lo[n][k] = split(W[k][n]), zero-padded ----------
__global__ void k_prep(const float* __restrict__ W, __nv_bfloat16* __restrict__ Th,
                       __nv_bfloat16* __restrict__ Tl, int K, int Nw, int Kpad, int Npad) {
    int idx = blockIdx.x * blockDim.x + threadIdx.x;
    if (idx >= Npad * Kpad) return;
    int n = idx / Kpad, k = idx % Kpad;
    float v = (k < K && n < Nw) ? W[(size_t)k * Nw + n] : 0.f;
    __nv_bfloat16 h = __float2bfloat16_rn(v);
    __nv_bfloat16 l = __float2bfloat16_rn(v - __bfloat162float(h));
    Th[idx] = h;
    Tl[idx] = l;
}

// ------- mma.sync bf16 split-precision GEMM ---------------------------------
// C[M,Nc] = act(A[M,K] @ W[K,Nc] + bias); W pre-transposed/split bf16 [Npad][Kpad].
// Block tile 128x128, K-chunk 32, 8 warps of 32x64 each. 3 products: HH+LH+HL.
#define LDW 20   // smem row stride in u32 (= 40 bf16 = 32 data + 8 pad)

__global__ void __launch_bounds__(256, 2)
k_mma(const float* __restrict__ A, const __nv_bfloat16* __restrict__ Bh,
      const __nv_bfloat16* __restrict__ Bl, const float* __restrict__ bias,
      float* __restrict__ C, int M, int K, int Kpad, int Nc, int relu) {
    __shared__ uint32_t AsH[128 * LDW], AsL[128 * LDW];
    __shared__ uint32_t BsH[128 * LDW], BsL[128 * LDW];

    int tid = threadIdx.x;
    int wid = tid >> 5, lane = tid & 31;
    int br = blockIdx.y * 128;
    int bc = blockIdx.x * 128;
    int wm = (wid & 3) * 32;       // warp row offset
    int wn = (wid >> 2) * 64;      // warp col offset

    const uint32_t* BhU = (const uint32_t*)Bh;
    const uint32_t* BlU = (const uint32_t*)Bl;

    uint32_t aBaseH = smem_u32(AsH), aBaseL = smem_u32(AsL);
    uint32_t bBaseH = smem_u32(BsH), bBaseL = smem_u32(BsL);

    // per-thread ldmatrix byte offsets (add kk*2 at use)
    uint32_t aOff[2], bOff[4];
    #pragma unroll
    for (int mt = 0; mt < 2; mt++)
        aOff[mt] = ((wm + mt * 16 + (lane & 15)) * 40 + ((lane >> 4) << 3)) * 2;
    #pragma unroll
    for (int ng = 0; ng < 4; ng++)
        bOff[ng] = ((wn + ng * 16 + (lane & 7) + ((lane >> 4) << 3)) * 40 + (((lane >> 3) & 1) << 3)) * 2;

    float acc[2][8][4];
    #pragma unroll
    for (int i = 0; i < 2; i++)
        #pragma unroll
        for (int j = 0; j < 8; j++)
            #pragma unroll
            for (int p = 0; p < 4; p++) acc[i][j][p] = 0.f;

    int nkc = Kpad >> 5;
    for (int kc = 0; kc < nkc; kc++) {
        int k0 = kc << 5;
        // ---- stage A chunk (fp32 -> bf16 hi/lo) : 128 rows x 32 k ----
        #pragma unroll
        for (int i = 0; i < 8; i++) {
            int idx = tid + (i << 8);      // 0..2047 (pairs)
            int row = idx >> 4, kp = idx & 15;
            int gm = br + row, gk = k0 + (kp << 1);
            float v0 = 0.f, v1 = 0.f;
            if (gm < M) {
                if (gk < K)     v0 = __ldg(&A[(size_t)gm * K + gk]);
                if (gk + 1 < K) v1 = __ldg(&A[(size_t)gm * K + gk + 1]);
            }
            __nv_bfloat16 h0 = __float2bfloat16_rn(v0);
            __nv_bfloat16 h1 = __float2bfloat16_rn(v1);
            __nv_bfloat16 l0 = __float2bfloat16_rn(v0 - __bfloat162float(h0));
            __nv_bfloat16 l1 = __float2bfloat16_rn(v1 - __bfloat162float(h1));
            AsH[row * LDW + kp] = (uint32_t)__bfloat16_as_ushort(h0) | ((uint32_t)__bfloat16_as_ushort(h1) << 16);
            AsL[row * LDW + kp] = (uint32_t)__bfloat16_as_ushort(l0) | ((uint32_t)__bfloat16_as_ushort(l1) << 16);
        }
        // ---- stage B chunk (pre-split) : 128 n x 32 k ----
        #pragma unroll
        for (int i = 0; i < 8; i++) {
            int idx = tid + (i << 8);
            int n = idx >> 4, kp = idx & 15;
            size_t g = (((size_t)(bc + n) * Kpad + k0) >> 1) + kp;
            BsH[n * LDW + kp] = __ldg(&BhU[g]);
            BsL[n * LDW + kp] = __ldg(&BlU[g]);
        }
        __syncthreads();

        #pragma unroll
        for (int kk = 0; kk < 32; kk += 16) {
            uint32_t aH[2][4], aL[2][4], bb[8][2];
            // A_hi
            #pragma unroll
            for (int mt = 0; mt < 2; mt++) ldsm4(aBaseH + aOff[mt] + kk * 2, aH[mt]);
            // B_hi
            #pragma unroll
            for (int ng = 0; ng < 4; ng++) ldsm4(bBaseH + bOff[ng] + kk * 2, &bb[2 * ng][0]);
            // HH
            #pragma unroll
            for (int mt = 0; mt < 2; mt++)
                #pragma unroll
                for (int nt = 0; nt < 8; nt++) mma16816(acc[mt][nt], aH[mt], bb[nt]);
            // A_lo ; LH
            #pragma unroll
            for (int mt = 0; mt < 2; mt++) ldsm4(aBaseL + aOff[mt] + kk * 2, aL[mt]);
            #pragma unroll
            for (int mt = 0; mt < 2; mt++)
                #pragma unroll
                for (int nt = 0; nt < 8; nt++) mma16816(acc[mt][nt], aL[mt], bb[nt]);
            // B_lo (reuse bb) ; HL
            #pragma unroll
            for (int ng = 0; ng < 4; ng++) ldsm4(bBaseL + bOff[ng] + kk * 2, &bb[2 * ng][0]);
            #pragma unroll
            for (int mt = 0; mt < 2; mt++)
                #pragma unroll
                for (int nt = 0; nt < 8; nt++) mma16816(acc[mt][nt], aH[mt], bb[nt]);
        }
        __syncthreads();
    }

    // ---- epilogue: bias + relu + store ----
    #pragma unroll
    for (int mt = 0; mt < 2; mt++) {
        int r0 = br + wm + mt * 16 + (lane >> 2);
        #pragma unroll
        for (int nt = 0; nt < 8; nt++) {
            int gn = bc + wn + nt * 8 + ((lane & 3) << 1);
            if (gn + 1 >= Nc + 1 && gn >= Nc) continue;
            float bv0 = (gn < Nc) ? bias[gn] : 0.f;
            float bv1 = (gn + 1 < Nc) ? bias[gn + 1] : 0.f;
            float c0 = acc[mt][nt][0] + bv0, c1 = acc[mt][nt][1] + bv1;
            float c2 = acc[mt][nt][2] + bv0, c3 = acc[mt][nt][3] + bv1;
            if (relu) {
                c0 = fmaxf(c0, 0.f); c1 = fmaxf(c1, 0.f);
                c2 = fmaxf(c2, 0.f); c3 = fmaxf(c3, 0.f);
            }
            if (gn + 1 < Nc) {
                if (r0 < M) { float2 v = {c0, c1}; *(float2*)&C[(size_t)r0 * Nc + gn] = v; }
                if (r0 + 8 < M) { float2 v = {c2, c3}; *(float2*)&C[(size_t)(r0 + 8) * Nc + gn] = v; }
            } else if (gn < Nc) {
                if (r0 < M) C[(size_t)r0 * Nc + gn] = c0;
                if (r0 + 8 < M) C[(size_t)(r0 + 8) * Nc + gn] = c2;
            }
        }
    }
}

// ---------------- BatchNorm statistics over z[NN,128] -----------------------
__global__ void k_bnstat(const float* __restrict__ z) {
    int col = threadIdx.x & 127;
    int half = threadIdx.x >> 7;
    float s = 0.f, s2 = 0.f;
    for (int r = blockIdx.x * 2 + half; r < NN; r += gridDim.x * 2) {
        float v = z[r * 128 + col];
        s += v; s2 += v * v;
    }
    __shared__ float sh[256], sh2[256];
    sh[threadIdx.x] = s; sh2[threadIdx.x] = s2;
    __syncthreads();
    if (threadIdx.x < 128) {
        atomicAdd(&g_bnsum[col], sh[threadIdx.x] + sh[threadIdx.x + 128]);
        atomicAdd(&g_bnsum[128 + col], sh2[threadIdx.x] + sh2[threadIdx.x + 128]);
    }
}
__global__ void k_bncoef(const float* __restrict__ gamma, const float* __restrict__ beta) {
    int c = threadIdx.x;
    float inv = 1.0f / (float)NN;
    float mu = g_bnsum[c] * inv;
    float var = g_bnsum[128 + c] * inv - mu * mu;
    float sc = gamma[c] * rsqrtf(var + 1e-5f);
    g_bncoef[c] = sc;
    g_bncoef[128 + c] = beta[c] - mu * sc;
}

// ------- final: BN affine + ReLU + [128x19] GEMV + log_softmax --------------
__global__ void k_final_out(const float* __restrict__ z, const float* __restrict__ W,
                            const float* __restrict__ b, float* __restrict__ out) {
    int gw = (blockIdx.x * blockDim.x + threadIdx.x) >> 5;
    if (gw >= NN) return;
    int lane = threadIdx.x & 31;
    float h[4];
    #pragma unroll
    for (int u = 0; u < 4; u++) {
        int c = lane + 32 * u;
        float v = z[gw * 128 + c];
        h[u] = fmaxf(v * g_bncoef[c] + g_bncoef[128 + c], 0.f);
    }
    float acc = (lane < 19) ? b[lane] : 0.f;
    #pragma unroll
    for (int u = 0; u < 4; u++) {
        #pragma unroll
        for (int l = 0; l < 32; l++) {
            float hb = __shfl_sync(0xffffffffu, h[u], l);
            if (lane < 19) acc += hb * __ldg(&W[(u * 32 + l) * 19 + lane]);
        }
    }
    float v = (lane < 19) ? acc : -3.4e38f;
    float m = v;
    #pragma unroll
    for (int off = 16; off > 0; off >>= 1) m = fmaxf(m, __shfl_xor_sync(0xffffffffu, m, off));
    float ex = (lane < 19) ? expf(v - m) : 0.f;
    float ssum = ex;
    #pragma unroll
    for (int off = 16; off > 0; off >>= 1) ssum += __shfl_xor_sync(0xffffffffu, ssum, off);
    if (lane < 19) out[gw * 19 + lane] = v - m - logf(ssum);
}

// ---------------------------------------------------------------------------
extern "C" void kernel_launch(void* const* d_in, const int* in_sizes, int n_in,
                              void* d_out, int out_size) {
    const float* x     = (const float*)d_in[0];
    const int*   ei    = (const int*)d_in[1];
    const float* W1    = (const float*)d_in[2];
    const float* b1    = (const float*)d_in[3];
    const float* W2    = (const float*)d_in[4];
    const float* b2    = (const float*)d_in[5];
    const float* W3    = (const float*)d_in[6];
    const float* b3    = (const float*)d_in[7];
    const float* fc1W  = (const float*)d_in[8];
    const float* fc1b  = (const float*)d_in[9];
    const float* fc2aW = (const float*)d_in[10];
    const float* fc2ab = (const float*)d_in[11];
    const float* gamma = (const float*)d_in[12];
    const float* beta  = (const float*)d_in[13];
    const float* fc2bW = (const float*)d_in[14];
    const float* fc2bb = (const float*)d_in[15];
    float* out = (float*)d_out;

    const int* src = ei;
    const int* dst = ei + EE;

    float *bufA, *bufB;
    cudaGetSymbolAddress((void**)&bufA, g_bufA);
    cudaGetSymbolAddress((void**)&bufB, g_bufB);
    __nv_bfloat16 *w1h, *w1l, *w2h, *w2l, *w3h, *w3l, *f1h, *f1l, *f2h, *f2l;
    cudaGetSymbolAddress((void**)&w1h, g_w1h);
    cudaGetSymbolAddress((void**)&w1l, g_w1l);
    cudaGetSymbolAddress((void**)&w2h, g_w2h);
    cudaGetSymbolAddress((void**)&w2l, g_w2l);
    cudaGetSymbolAddress((void**)&w3h, g_w3h);
    cudaGetSymbolAddress((void**)&w3l, g_w3l);
    cudaGetSymbolAddress((void**)&f1h, g_f1h);
    cudaGetSymbolAddress((void**)&f1l, g_f1l);
    cudaGetSymbolAddress((void**)&f2h, g_f2h);
    cudaGetSymbolAddress((void**)&f2l, g_f2l);

    // CSR build
    k_zero<<<(NN + 255) / 256, 256>>>();
    k_count<<<(EE + 255) / 256, 256>>>(dst);
    k_scan1<<<(NN + 1023) / 1024, 1024>>>();
    k_scan2<<<1, 128>>>((NN + 1023) / 1024);
    k_rowptr<<<(NN + 255) / 256, 256>>>();
    k_fill<<<(EE + 255) / 256, 256>>>(src, dst);

    // weight prep (transposed + bf16 hi/lo split, zero-padded)
    k_prep<<<(128 * 128 + 255) / 256, 256>>>(W1, w1h, w1l, 100, 100, 128, 128);
    k_prep<<<(128 * 128 + 255) / 256, 256>>>(W2, w2h, w2l, 100, 100, 128, 128);
    k_prep<<<(256 * 128 + 255) / 256, 256>>>(W3, w3h, w3l, 100, 256, 128, 256);
    k_prep<<<(256 * 256 + 255) / 256, 256>>>(fc1W, f1h, f1l, 256, 256, 256, 256);
    k_prep<<<(128 * 256 + 255) / 256, 256>>>(fc2aW, f2h, f2l, 256, 128, 256, 128);

    const int aggBlocks = (NN * 32 + 255) / 256;
    const int gy = (NN + 127) / 128;  // 782

    // conv1: a = Ahat clip(x); h = relu(a W1 + b1)
    k_agg<<<aggBlocks, 256>>>(x, bufB, 1);
    k_mma<<<dim3(1, gy), 256>>>(bufB, w1h, w1l, b1, bufA, NN, 100, 128, 100, 1);
    // conv2
    k_agg<<<aggBlocks, 256>>>(bufA, bufB, 0);
    k_mma<<<dim3(1, gy), 256>>>(bufB, w2h, w2l, b2, bufA, NN, 100, 128, 100, 1);
    // conv3: [NN,100] @ [100,256]
    k_agg<<<aggBlocks, 256>>>(bufA, bufB, 0);
    k_mma<<<dim3(2, gy), 256>>>(bufB, w3h, w3l, b3, bufA, NN, 100, 128, 256, 1);
    // fc1: [NN,256] @ [256,256]
    k_mma<<<dim3(2, gy), 256>>>(bufA, f1h, f1l, fc1b, bufB, NN, 256, 256, 256, 1);
    // fc2a: [NN,256] @ [256,128] (no relu; BN next)
    k_mma<<<dim3(1, gy), 256>>>(bufB, f2h, f2l, fc2ab, bufA, NN, 256, 256, 128, 0);
    // BN + final
    k_bnstat<<<512, 256>>>(bufA);
    k_bncoef<<<1, 128>>>(gamma, beta);
    k_final_out<<<aggBlocks, 256>>>(bufA, fc2bW, fc2bb, out);
}

// round 5
// speedup vs baseline: 2.1387x; 1.2857x over previous
#include <cuda_runtime.h>
#include <cuda_bf16.h>
#include <math.h>
#include <stdint.h>

#define NN 100000
#define EE 1600000
#define FIN 100

typedef unsigned long long ull;

// ---------------- scratch (static device allocations) ----------------
__device__ float g_bufA[NN * 256];
__device__ __align__(16) __nv_bfloat16 g_p0h[NN * 256], g_p0l[NN * 256];  // activation pair 0
__device__ __align__(16) __nv_bfloat16 g_p1h[NN * 256], g_p1l[NN * 256];  // activation pair 1
__device__ int   g_deg[NN];
__device__ int   g_incl[NN];
__device__ int   g_rowptr[NN + 1];
__device__ int   g_cursor[NN];
__device__ int   g_col[EE];
__device__ float g_dinv[NN];
__device__ int   g_part[128];
__device__ float g_bnsum[256];
__device__ float g_bncoef[256];
// transposed + split weights (bf16), [Npad][Kpad]
__device__ __align__(16) __nv_bfloat16 g_w1h[128 * 128], g_w1l[128 * 128];
__device__ __align__(16) __nv_bfloat16 g_w2h[128 * 128], g_w2l[128 * 128];
__device__ __align__(16) __nv_bfloat16 g_w3h[256 * 128], g_w3l[256 * 128];
__device__ __align__(16) __nv_bfloat16 g_f1h[256 * 256], g_f1l[256 * 256];
__device__ __align__(16) __nv_bfloat16 g_f2h[128 * 256], g_f2l[128 * 256];

// ---------------- PTX helpers ----------------
__device__ __forceinline__ uint32_t smem_u32(const void* p) {
    uint32_t a;
    asm("{ .reg .u64 t; cvta.to.shared.u64 t, %1; cvt.u32.u64 %0, t; }" : "=r"(a) : "l"(p));
    return a;
}
__device__ __forceinline__ void ldsm4(uint32_t addr, uint32_t* r) {
    asm volatile("ldmatrix.sync.aligned.m8n8.x4.shared.b16 {%0,%1,%2,%3}, [%4];"
                 : "=r"(r[0]), "=r"(r[1]), "=r"(r[2]), "=r"(r[3]) : "r"(addr));
}
__device__ __forceinline__ void mma16816(float* d, const uint32_t* a, const uint32_t* b) {
    asm volatile(
        "mma.sync.aligned.m16n8k16.row.col.f32.bf16.bf16.f32 "
        "{%0,%1,%2,%3}, {%4,%5,%6,%7}, {%8,%9}, {%0,%1,%2,%3};"
        : "+f"(d[0]), "+f"(d[1]), "+f"(d[2]), "+f"(d[3])
        : "r"(a[0]), "r"(a[1]), "r"(a[2]), "r"(a[3]), "r"(b[0]), "r"(b[1]));
}
__device__ __forceinline__ uint32_t pack_hi(float a, float b) {
    __nv_bfloat16 h0 = __float2bfloat16_rn(a), h1 = __float2bfloat16_rn(b);
    return (uint32_t)__bfloat16_as_ushort(h0) | ((uint32_t)__bfloat16_as_ushort(h1) << 16);
}
__device__ __forceinline__ uint32_t pack_lo(float a, float b) {
    __nv_bfloat16 h0 = __float2bfloat16_rn(a), h1 = __float2bfloat16_rn(b);
    __nv_bfloat16 l0 = __float2bfloat16_rn(a - __bfloat162float(h0));
    __nv_bfloat16 l1 = __float2bfloat16_rn(b - __bfloat162float(h1));
    return (uint32_t)__bfloat16_as_ushort(l0) | ((uint32_t)__bfloat16_as_ushort(l1) << 16);
}

// ---------------- CSR build ----------------
__global__ void k_zero() {
    int i = blockIdx.x * blockDim.x + threadIdx.x;
    if (i < NN) g_deg[i] = 0;
    if (i < 256) g_bnsum[i] = 0.0f;
}
__global__ void k_count(const int* __restrict__ dst) {
    int e = blockIdx.x * blockDim.x + threadIdx.x;
    if (e < EE) atomicAdd(&g_deg[dst[e]], 1);
}
__global__ void k_scan1() {
    __shared__ int sh[1024];
    int i = blockIdx.x * 1024 + threadIdx.x;
    int v = (i < NN) ? g_deg[i] : 0;
    sh[threadIdx.x] = v;
    __syncthreads();
    for (int off = 1; off < 1024; off <<= 1) {
        int t = (threadIdx.x >= (unsigned)off) ? sh[threadIdx.x - off] : 0;
        __syncthreads();
        sh[threadIdx.x] += t;
        __syncthreads();
    }
    if (i < NN) g_incl[i] = sh[threadIdx.x];
    if (threadIdx.x == 1023) g_part[blockIdx.x] = sh[1023];
}
__global__ void k_scan2(int nb) {
    __shared__ int sh[128];
    int t = threadIdx.x;
    sh[t] = (t < nb) ? g_part[t] : 0;
    __syncthreads();
    for (int off = 1; off < 128; off <<= 1) {
        int u = (t >= off) ? sh[t - off] : 0;
        __syncthreads();
        sh[t] += u;
        __syncthreads();
    }
    g_part[t] = (t == 0) ? 0 : sh[t - 1];
}
__global__ void k_rowptr() {
    int i = blockIdx.x * blockDim.x + threadIdx.x;
    if (i >= NN) return;
    int excl = g_incl[i] - g_deg[i] + g_part[i >> 10];
    g_rowptr[i] = excl;
    g_cursor[i] = excl;
    g_dinv[i] = rsqrtf((float)g_deg[i] + 1.0f);
    if (i == NN - 1) g_rowptr[NN] = g_incl[i] + g_part[i >> 10];
}
__global__ void k_fill(const int* __restrict__ src, const int* __restrict__ dst) {
    int e = blockIdx.x * blockDim.x + threadIdx.x;
    if (e >= EE) return;
    int p = atomicAdd(&g_cursor[dst[e]], 1);
    g_col[p] = src[e];
}

// -------- aggregation: out(bf16 hi/lo, Kpad=128) = Ahat * in[.,100] ---------
__global__ void k_aggb(const float* __restrict__ in,
                       __nv_bfloat16* __restrict__ oh, __nv_bfloat16* __restrict__ ol,
                       int clip) {
    int gw = (blockIdx.x * blockDim.x + threadIdx.x) >> 5;
    if (gw >= NN) return;
    int lane = threadIdx.x & 31;
    bool act = lane < 25;                 // 25*4 = 100 cols
    int c4 = lane << 2;
    float di = g_dinv[gw];
    int s0 = g_rowptr[gw], s1 = g_rowptr[gw + 1];
    float a0 = 0.f, a1 = 0.f, a2 = 0.f, a3 = 0.f;
    for (int e = s0; e < s1; e++) {
        int s = __ldg(&g_col[e]);
        float nr = __ldg(&g_dinv[s]) * di;
        if (act) {
            float4 v = __ldg((const float4*)(in + (size_t)s * FIN + c4));
            if (clip) {
                v.x = fminf(fmaxf(v.x, -0.4f), 0.4f);
                v.y = fminf(fmaxf(v.y, -0.4f), 0.4f);
                v.z = fminf(fmaxf(v.z, -0.4f), 0.4f);
                v.w = fminf(fmaxf(v.w, -0.4f), 0.4f);
            }
            a0 += nr * v.x; a1 += nr * v.y; a2 += nr * v.z; a3 += nr * v.w;
        }
    }
    if (act) {   // self loop
        float nn = di * di;
        float4 v = *(const float4*)(in + (size_t)gw * FIN + c4);
        if (clip) {
            v.x = fminf(fmaxf(v.x, -0.4f), 0.4f);
            v.y = fminf(fmaxf(v.y, -0.4f), 0.4f);
            v.z = fminf(fmaxf(v.z, -0.4f), 0.4f);
            v.w = fminf(fmaxf(v.w, -0.4f), 0.4f);
        }
        a0 += nn * v.x; a1 += nn * v.y; a2 += nn * v.z; a3 += nn * v.w;
    }
    // write 4 bf16 (8 bytes) to hi and lo arrays; lanes >= 25 write zero pad
    uint2 ph = {0u, 0u}, pl = {0u, 0u};
    if (act) {
        ph.x = pack_hi(a0, a1); ph.y = pack_hi(a2, a3);
        pl.x = pack_lo(a0, a1); pl.y = pack_lo(a2, a3);
    }
    size_t o = ((size_t)gw * 128 + c4) >> 2;   // uint2 units
    ((uint2*)oh)[o] = ph;
    ((uint2*)ol)[o] = pl;
}

// ------- weight prep: Wt_hi/lo[n][k] = split(W[k][n]), zero-padded ----------
__global__ void k_prep(const float* __restrict__ W, __nv_bfloat16* __restrict__ Th,
                       __nv_bfloat16* __restrict__ Tl, int K, int Nw, int Kpad, int Npad) {
    int idx = blockIdx.x * blockDim.x + threadIdx.x;
    if (idx >= Npad * Kpad) return;
    int n = idx / Kpad, k = idx % Kpad;
    float v = (k < K && n < Nw) ? W[(size_t)k * Nw + n] : 0.f;
    __nv_bfloat16 h = __float2bfloat16_rn(v);
    __nv_bfloat16 l = __float2bfloat16_rn(v - __bfloat162float(h));
    Th[idx] = h;
    Tl[idx] = l;
}

// ------- mma.sync bf16 split-precision GEMM, pre-split operands -------------
// C = act(A @ W + bias); A as hi/lo bf16 [M][Kpad], W as hi/lo bf16 [Npad][Kpad].
// outmode 0: fp32 C[M][Nc];  outmode 1: bf16 hi/lo pair Ch/Cl [M][Nc].
#define LDW 20   // smem row stride in u32 (40 bf16 = 32 data + 8 pad)

__global__ void __launch_bounds__(256, 2)
k_mma(const __nv_bfloat16* __restrict__ Ah, const __nv_bfloat16* __restrict__ Al,
      const __nv_bfloat16* __restrict__ Bh, const __nv_bfloat16* __restrict__ Bl,
      const float* __restrict__ bias, float* __restrict__ C,
      __nv_bfloat16* __restrict__ Ch, __nv_bfloat16* __restrict__ Cl,
      int M, int Kpad, int Nc, int relu, int outmode) {
    __shared__ uint32_t AsH[128 * LDW], AsL[128 * LDW];
    __shared__ uint32_t BsH[128 * LDW], BsL[128 * LDW];

    int tid = threadIdx.x;
    int wid = tid >> 5, lane = tid & 31;
    int br = blockIdx.y * 128;
    int bc = blockIdx.x * 128;
    int wm = (wid & 3) * 32;
    int wn = (wid >> 2) * 64;

    uint32_t aBaseH = smem_u32(AsH), aBaseL = smem_u32(AsL);
    uint32_t bBaseH = smem_u32(BsH), bBaseL = smem_u32(BsL);

    uint32_t aOff[2], bOff[4];
    #pragma unroll
    for (int mt = 0; mt < 2; mt++)
        aOff[mt] = ((wm + mt * 16 + (lane & 15)) * 40 + ((lane >> 4) << 3)) * 2;
    #pragma unroll
    for (int ng = 0; ng < 4; ng++)
        bOff[ng] = ((wn + ng * 16 + (lane & 7) + ((lane >> 4) << 3)) * 40 + (((lane >> 3) & 1) << 3)) * 2;

    float acc[2][8][4];
    #pragma unroll
    for (int i = 0; i < 2; i++)
        #pragma unroll
        for (int j = 0; j < 8; j++)
            #pragma unroll
            for (int p = 0; p < 4; p++) acc[i][j][p] = 0.f;

    int nkc = Kpad >> 5;
    for (int kc = 0; kc < nkc; kc++) {
        int k0 = kc << 5;
        // ---- stage A chunk: 128 rows x 32 k, both arrays, vector copies ----
        #pragma unroll
        for (int j = 0; j < 2; j++) {
            int idx = tid + (j << 8);          // 0..511
            int row = idx >> 2, g = idx & 3;
            int gm = br + row;
            uint4 vh = make_uint4(0, 0, 0, 0), vl = make_uint4(0, 0, 0, 0);
            if (gm < M) {
                size_t base = (((size_t)gm * Kpad + k0) >> 3) + g;   // uint4 units
                vh = __ldg(&((const uint4*)Ah)[base]);
                vl = __ldg(&((const uint4*)Al)[base]);
            }
            *(uint4*)&AsH[row * LDW + (g << 2)] = vh;
            *(uint4*)&AsL[row * LDW + (g << 2)] = vl;
        }
        // ---- stage B chunk: 128 n-rows x 32 k ----
        #pragma unroll
        for (int j = 0; j < 2; j++) {
            int idx = tid + (j << 8);
            int row = idx >> 2, g = idx & 3;
            size_t base = (((size_t)(bc + row) * Kpad + k0) >> 3) + g;
            *(uint4*)&BsH[row * LDW + (g << 2)] = __ldg(&((const uint4*)Bh)[base]);
            *(uint4*)&BsL[row * LDW + (g << 2)] = __ldg(&((const uint4*)Bl)[base]);
        }
        __syncthreads();

        #pragma unroll
        for (int kk = 0; kk < 32; kk += 16) {
            uint32_t aH[2][4], aL[2][4], bb[8][2];
            #pragma unroll
            for (int mt = 0; mt < 2; mt++) ldsm4(aBaseH + aOff[mt] + kk * 2, aH[mt]);
            #pragma unroll
            for (int ng = 0; ng < 4; ng++) ldsm4(bBaseH + bOff[ng] + kk * 2, &bb[2 * ng][0]);
            #pragma unroll
            for (int mt = 0; mt < 2; mt++)
                #pragma unroll
                for (int nt = 0; nt < 8; nt++) mma16816(acc[mt][nt], aH[mt], bb[nt]);
            #pragma unroll
            for (int mt = 0; mt < 2; mt++) ldsm4(aBaseL + aOff[mt] + kk * 2, aL[mt]);
            #pragma unroll
            for (int mt = 0; mt < 2; mt++)
                #pragma unroll
                for (int nt = 0; nt < 8; nt++) mma16816(acc[mt][nt], aL[mt], bb[nt]);
            #pragma unroll
            for (int ng = 0; ng < 4; ng++) ldsm4(bBaseL + bOff[ng] + kk * 2, &bb[2 * ng][0]);
            #pragma unroll
            for (int mt = 0; mt < 2; mt++)
                #pragma unroll
                for (int nt = 0; nt < 8; nt++) mma16816(acc[mt][nt], aH[mt], bb[nt]);
        }
        __syncthreads();
    }

    // ---- epilogue ----
    #pragma unroll
    for (int mt = 0; mt < 2; mt++) {
        int r0 = br + wm + mt * 16 + (lane >> 2);
        #pragma unroll
        for (int nt = 0; nt < 8; nt++) {
            int gn = bc + wn + nt * 8 + ((lane & 3) << 1);
            float bv0 = (gn < Nc) ? bias[gn] : 0.f;
            float bv1 = (gn + 1 < Nc) ? bias[gn + 1] : 0.f;
            float c0 = acc[mt][nt][0] + bv0, c1 = acc[mt][nt][1] + bv1;
            float c2 = acc[mt][nt][2] + bv0, c3 = acc[mt][nt][3] + bv1;
            if (relu) {
                c0 = fmaxf(c0, 0.f); c1 = fmaxf(c1, 0.f);
                c2 = fmaxf(c2, 0.f); c3 = fmaxf(c3, 0.f);
            }
            if (outmode == 0) {
                if (gn + 1 < Nc) {
                    if (r0 < M) { float2 v = {c0, c1}; *(float2*)&C[(size_t)r0 * Nc + gn] = v; }
                    if (r0 + 8 < M) { float2 v = {c2, c3}; *(float2*)&C[(size_t)(r0 + 8) * Nc + gn] = v; }
                } else if (gn < Nc) {
                    if (r0 < M) C[(size_t)r0 * Nc + gn] = c0;
                    if (r0 + 8 < M) C[(size_t)(r0 + 8) * Nc + gn] = c2;
                }
            } else {
                if (gn + 1 < Nc) {
                    if (r0 < M) {
                        size_t o = ((size_t)r0 * Nc + gn) >> 1;
                        ((uint32_t*)Ch)[o] = pack_hi(c0, c1);
                        ((uint32_t*)Cl)[o] = pack_lo(c0, c1);
                    }
                    if (r0 + 8 < M) {
                        size_t o = ((size_t)(r0 + 8) * Nc + gn) >> 1;
                        ((uint32_t*)Ch)[o] = pack_hi(c2, c3);
                        ((uint32_t*)Cl)[o] = pack_lo(c2, c3);
                    }
                }
            }
        }
    }
}

// ---------------- BatchNorm statistics over z[NN,128] -----------------------
__global__ void k_bnstat(const float* __restrict__ z) {
    int col = threadIdx.x & 127;
    int half = threadIdx.x >> 7;
    float s = 0.f, s2 = 0.f;
    for (int r = blockIdx.x * 2 + half; r < NN; r += gridDim.x * 2) {
        float v = z[r * 128 + col];
        s += v; s2 += v * v;
    }
    __shared__ float sh[256], sh2[256];
    sh[threadIdx.x] = s; sh2[threadIdx.x] = s2;
    __syncthreads();
    if (threadIdx.x < 128) {
        atomicAdd(&g_bnsum[col], sh[threadIdx.x] + sh[threadIdx.x + 128]);
        atomicAdd(&g_bnsum[128 + col], sh2[threadIdx.x] + sh2[threadIdx.x + 128]);
    }
}
__global__ void k_bncoef(const float* __restrict__ gamma, const float* __restrict__ beta) {
    int c = threadIdx.x;
    float inv = 1.0f / (float)NN;
    float mu = g_bnsum[c] * inv;
    float var = g_bnsum[128 + c] * inv - mu * mu;
    float sc = gamma[c] * rsqrtf(var + 1e-5f);
    g_bncoef[c] = sc;
    g_bncoef[128 + c] = beta[c] - mu * sc;
}

// ------- final: BN affine + ReLU + [128x19] GEMV + log_softmax --------------
__global__ void k_final_out(const float* __restrict__ z, const float* __restrict__ W,
                            const float* __restrict__ b, float* __restrict__ out) {
    int gw = (blockIdx.x * blockDim.x + threadIdx.x) >> 5;
    if (gw >= NN) return;
    int lane = threadIdx.x & 31;
    float h[4];
    #pragma unroll
    for (int u = 0; u < 4; u++) {
        int c = lane + 32 * u;
        float v = z[gw * 128 + c];
        h[u] = fmaxf(v * g_bncoef[c] + g_bncoef[128 + c], 0.f);
    }
    float acc = (lane < 19) ? b[lane] : 0.f;
    #pragma unroll
    for (int u = 0; u < 4; u++) {
        #pragma unroll
        for (int l = 0; l < 32; l++) {
            float hb = __shfl_sync(0xffffffffu, h[u], l);
            if (lane < 19) acc += hb * __ldg(&W[(u * 32 + l) * 19 + lane]);
        }
    }
    float v = (lane < 19) ? acc : -3.4e38f;
    float m = v;
    #pragma unroll
    for (int off = 16; off > 0; off >>= 1) m = fmaxf(m, __shfl_xor_sync(0xffffffffu, m, off));
    float ex = (lane < 19) ? expf(v - m) : 0.f;
    float ssum = ex;
    #pragma unroll
    for (int off = 16; off > 0; off >>= 1) ssum += __shfl_xor_sync(0xffffffffu, ssum, off);
    if (lane < 19) out[gw * 19 + lane] = v - m - logf(ssum);
}

// ---------------------------------------------------------------------------
extern "C" void kernel_launch(void* const* d_in, const int* in_sizes, int n_in,
                              void* d_out, int out_size) {
    const float* x     = (const float*)d_in[0];
    const int*   ei    = (const int*)d_in[1];
    const float* W1    = (const float*)d_in[2];
    const float* b1    = (const float*)d_in[3];
    const float* W2    = (const float*)d_in[4];
    const float* b2    = (const float*)d_in[5];
    const float* W3    = (const float*)d_in[6];
    const float* b3    = (const float*)d_in[7];
    const float* fc1W  = (const float*)d_in[8];
    const float* fc1b  = (const float*)d_in[9];
    const float* fc2aW = (const float*)d_in[10];
    const float* fc2ab = (const float*)d_in[11];
    const float* gamma = (const float*)d_in[12];
    const float* beta  = (const float*)d_in[13];
    const float* fc2bW = (const float*)d_in[14];
    const float* fc2bb = (const float*)d_in[15];
    float* out = (float*)d_out;

    const int* src = ei;
    const int* dst = ei + EE;

    float* bufA;
    cudaGetSymbolAddress((void**)&bufA, g_bufA);
    __nv_bfloat16 *p0h, *p0l, *p1h, *p1l;
    cudaGetSymbolAddress((void**)&p0h, g_p0h);
    cudaGetSymbolAddress((void**)&p0l, g_p0l);
    cudaGetSymbolAddress((void**)&p1h, g_p1h);
    cudaGetSymbolAddress((void**)&p1l, g_p1l);
    __nv_bfloat16 *w1h, *w1l, *w2h, *w2l, *w3h, *w3l, *f1h, *f1l, *f2h, *f2l;
    cudaGetSymbolAddress((void**)&w1h, g_w1h);
    cudaGetSymbolAddress((void**)&w1l, g_w1l);
    cudaGetSymbolAddress((void**)&w2h, g_w2h);
    cudaGetSymbolAddress((void**)&w2l, g_w2l);
    cudaGetSymbolAddress((void**)&w3h, g_w3h);
    cudaGetSymbolAddress((void**)&w3l, g_w3l);
    cudaGetSymbolAddress((void**)&f1h, g_f1h);
    cudaGetSymbolAddress((void**)&f1l, g_f1l);
    cudaGetSymbolAddress((void**)&f2h, g_f2h);
    cudaGetSymbolAddress((void**)&f2l, g_f2l);

    // CSR build
    k_zero<<<(NN + 255) / 256, 256>>>();
    k_count<<<(EE + 255) / 256, 256>>>(dst);
    k_scan1<<<(NN + 1023) / 1024, 1024>>>();
    k_scan2<<<1, 128>>>((NN + 1023) / 1024);
    k_rowptr<<<(NN + 255) / 256, 256>>>();
    k_fill<<<(EE + 255) / 256, 256>>>(src, dst);

    // weight prep (transposed + bf16 hi/lo split, zero-padded)
    k_prep<<<(128 * 128 + 255) / 256, 256>>>(W1, w1h, w1l, 100, 100, 128, 128);
    k_prep<<<(128 * 128 + 255) / 256, 256>>>(W2, w2h, w2l, 100, 100, 128, 128);
    k_prep<<<(256 * 128 + 255) / 256, 256>>>(W3, w3h, w3l, 100, 256, 128, 256);
    k_prep<<<(256 * 256 + 255) / 256, 256>>>(fc1W, f1h, f1l, 256, 256, 256, 256);
    k_prep<<<(128 * 256 + 255) / 256, 256>>>(fc2aW, f2h, f2l, 256, 128, 256, 128);

    const int aggBlocks = (NN * 32 + 255) / 256;
    const int gy = (NN + 127) / 128;  // 782

    // conv1: P0 = split(Ahat clip(x)); bufA = relu(P0 @ W1 + b1)
    k_aggb<<<aggBlocks, 256>>>(x, p0h, p0l, 1);
    k_mma<<<dim3(1, gy), 256>>>(p0h, p0l, w1h, w1l, b1, bufA, 0, 0, NN, 128, 100, 1, 0);
    // conv2
    k_aggb<<<aggBlocks, 256>>>(bufA, p0h, p0l, 0);
    k_mma<<<dim3(1, gy), 256>>>(p0h, p0l, w2h, w2l, b2, bufA, 0, 0, NN, 128, 100, 1, 0);
    // conv3: [NN,100]@[100,256] -> bf16 hi/lo pair P1
    k_aggb<<<aggBlocks, 256>>>(bufA, p0h, p0l, 0);
    k_mma<<<dim3(2, gy), 256>>>(p0h, p0l, w3h, w3l, b3, 0, p1h, p1l, NN, 128, 256, 1, 1);
    // fc1: [NN,256]@[256,256] -> pair P0
    k_mma<<<dim3(2, gy), 256>>>(p1h, p1l, f1h, f1l, fc1b, 0, p0h, p0l, NN, 256, 256, 1, 1);
    // fc2a: [NN,256]@[256,128] -> fp32 bufA (BN next)
    k_mma<<<dim3(1, gy), 256>>>(p0h, p0l, f2h, f2l, fc2ab, bufA, 0, 0, NN, 256, 128, 0, 0);
    // BN + final
    k_bnstat<<<512, 256>>>(bufA);
    k_bncoef<<<1, 128>>>(gamma, beta);
    k_final_out<<<aggBlocks, 256>>>(bufA, fc2bW, fc2bb, out);
}

// round 6
// speedup vs baseline: 2.3648x; 1.1057x over previous
#include <cuda_runtime.h>
#include <cuda_bf16.h>
#include <math.h>
#include <stdint.h>

#define NN 100000
#define EE 1600000
#define FIN 100

typedef unsigned long long ull;

// ---------------- scratch (static device allocations) ----------------
__device__ float g_bufA[NN * 256];
__device__ __align__(16) __nv_bfloat16 g_p0h[NN * 256], g_p0l[NN * 256];
__device__ __align__(16) __nv_bfloat16 g_p1h[NN * 256], g_p1l[NN * 256];
__device__ int   g_deg[NN];
__device__ int   g_incl[NN];
__device__ int   g_rowptr[NN + 1];
__device__ int   g_cursor[NN];
__device__ int   g_col[EE];
__device__ float g_dinv[NN];
__device__ int   g_part[128];
__device__ float g_bnsum[256];
__device__ float g_bncoef[256];
__device__ __align__(16) __nv_bfloat16 g_w1h[128 * 128], g_w1l[128 * 128];
__device__ __align__(16) __nv_bfloat16 g_w2h[128 * 128], g_w2l[128 * 128];
__device__ __align__(16) __nv_bfloat16 g_w3h[256 * 128], g_w3l[256 * 128];
__device__ __align__(16) __nv_bfloat16 g_f1h[256 * 256], g_f1l[256 * 256];
__device__ __align__(16) __nv_bfloat16 g_f2h[128 * 256], g_f2l[128 * 256];

// ---------------- PTX helpers ----------------
__device__ __forceinline__ uint32_t smem_u32(const void* p) {
    uint32_t a;
    asm("{ .reg .u64 t; cvta.to.shared.u64 t, %1; cvt.u32.u64 %0, t; }" : "=r"(a) : "l"(p));
    return a;
}
__device__ __forceinline__ void ldsm4(uint32_t addr, uint32_t* r) {
    asm volatile("ldmatrix.sync.aligned.m8n8.x4.shared.b16 {%0,%1,%2,%3}, [%4];"
                 : "=r"(r[0]), "=r"(r[1]), "=r"(r[2]), "=r"(r[3]) : "r"(addr));
}
__device__ __forceinline__ void mma16816(float* d, const uint32_t* a, const uint32_t* b) {
    asm volatile(
        "mma.sync.aligned.m16n8k16.row.col.f32.bf16.bf16.f32 "
        "{%0,%1,%2,%3}, {%4,%5,%6,%7}, {%8,%9}, {%0,%1,%2,%3};"
        : "+f"(d[0]), "+f"(d[1]), "+f"(d[2]), "+f"(d[3])
        : "r"(a[0]), "r"(a[1]), "r"(a[2]), "r"(a[3]), "r"(b[0]), "r"(b[1]));
}
__device__ __forceinline__ void cp16(uint32_t s, const void* g) {
    asm volatile("cp.async.cg.shared.global [%0], [%1], 16;" :: "r"(s), "l"(g));
}
__device__ __forceinline__ void cp16z(uint32_t s, const void* g, int srcsz) {
    asm volatile("cp.async.cg.shared.global [%0], [%1], 16, %2;" :: "r"(s), "l"(g), "r"(srcsz));
}
#define CP_COMMIT() asm volatile("cp.async.commit_group;" ::: "memory")
#define CP_WAIT(n)  asm volatile("cp.async.wait_group %0;" :: "n"(n) : "memory")

__device__ __forceinline__ uint32_t pack_hi(float a, float b) {
    __nv_bfloat16 h0 = __float2bfloat16_rn(a), h1 = __float2bfloat16_rn(b);
    return (uint32_t)__bfloat16_as_ushort(h0) | ((uint32_t)__bfloat16_as_ushort(h1) << 16);
}
__device__ __forceinline__ uint32_t pack_lo(float a, float b) {
    __nv_bfloat16 h0 = __float2bfloat16_rn(a), h1 = __float2bfloat16_rn(b);
    __nv_bfloat16 l0 = __float2bfloat16_rn(a - __bfloat162float(h0));
    __nv_bfloat16 l1 = __float2bfloat16_rn(b - __bfloat162float(h1));
    return (uint32_t)__bfloat16_as_ushort(l0) | ((uint32_t)__bfloat16_as_ushort(l1) << 16);
}

// ---------------- CSR build ----------------
__global__ void k_zero() {
    int i = blockIdx.x * blockDim.x + threadIdx.x;
    if (i < NN) g_deg[i] = 0;
    if (i < 256) g_bnsum[i] = 0.0f;
}
__global__ void k_count(const int* __restrict__ dst) {
    int e = blockIdx.x * blockDim.x + threadIdx.x;
    if (e < EE) atomicAdd(&g_deg[dst[e]], 1);
}
__global__ void k_scan1() {
    __shared__ int sh[1024];
    int i = blockIdx.x * 1024 + threadIdx.x;
    int v = (i < NN) ? g_deg[i] : 0;
    sh[threadIdx.x] = v;
    __syncthreads();
    for (int off = 1; off < 1024; off <<= 1) {
        int t = (threadIdx.x >= (unsigned)off) ? sh[threadIdx.x - off] : 0;
        __syncthreads();
        sh[threadIdx.x] += t;
        __syncthreads();
    }
    if (i < NN) g_incl[i] = sh[threadIdx.x];
    if (threadIdx.x == 1023) g_part[blockIdx.x] = sh[1023];
}
__global__ void k_scan2(int nb) {
    __shared__ int sh[128];
    int t = threadIdx.x;
    sh[t] = (t < nb) ? g_part[t] : 0;
    __syncthreads();
    for (int off = 1; off < 128; off <<= 1) {
        int u = (t >= off) ? sh[t - off] : 0;
        __syncthreads();
        sh[t] += u;
        __syncthreads();
    }
    g_part[t] = (t == 0) ? 0 : sh[t - 1];
}
__global__ void k_rowptr() {
    int i = blockIdx.x * blockDim.x + threadIdx.x;
    if (i >= NN) return;
    int excl = g_incl[i] - g_deg[i] + g_part[i >> 10];
    g_rowptr[i] = excl;
    g_cursor[i] = excl;
    g_dinv[i] = rsqrtf((float)g_deg[i] + 1.0f);
    if (i == NN - 1) g_rowptr[NN] = g_incl[i] + g_part[i >> 10];
}
__global__ void k_fill(const int* __restrict__ src, const int* __restrict__ dst) {
    int e = blockIdx.x * blockDim.x + threadIdx.x;
    if (e >= EE) return;
    int p = atomicAdd(&g_cursor[dst[e]], 1);
    g_col[p] = src[e];
}

// -------- aggregation: out(bf16 hi/lo, Kpad=128) = Ahat * in[.,100] ---------
__global__ void k_aggb(const float* __restrict__ in,
                       __nv_bfloat16* __restrict__ oh, __nv_bfloat16* __restrict__ ol,
                       int clip) {
    int gw = (blockIdx.x * blockDim.x + threadIdx.x) >> 5;
    if (gw >= NN) return;
    int lane = threadIdx.x & 31;
    bool act = lane < 25;
    int c4 = lane << 2;
    float di = g_dinv[gw];
    int s0 = g_rowptr[gw], s1 = g_rowptr[gw + 1];
    float a0 = 0.f, a1 = 0.f, a2 = 0.f, a3 = 0.f;
    float b0 = 0.f, b1 = 0.f, b2 = 0.f, b3 = 0.f;
    int e = s0;
    for (; e + 1 < s1; e += 2) {
        int sA = __ldg(&g_col[e]);
        int sB = __ldg(&g_col[e + 1]);
        float nA = __ldg(&g_dinv[sA]) * di;
        float nB = __ldg(&g_dinv[sB]) * di;
        if (act) {
            float4 vA = __ldg((const float4*)(in + (size_t)sA * FIN + c4));
            float4 vB = __ldg((const float4*)(in + (size_t)sB * FIN + c4));
            if (clip) {
                vA.x = fminf(fmaxf(vA.x, -0.4f), 0.4f);
                vA.y = fminf(fmaxf(vA.y, -0.4f), 0.4f);
                vA.z = fminf(fmaxf(vA.z, -0.4f), 0.4f);
                vA.w = fminf(fmaxf(vA.w, -0.4f), 0.4f);
                vB.x = fminf(fmaxf(vB.x, -0.4f), 0.4f);
                vB.y = fminf(fmaxf(vB.y, -0.4f), 0.4f);
                vB.z = fminf(fmaxf(vB.z, -0.4f), 0.4f);
                vB.w = fminf(fmaxf(vB.w, -0.4f), 0.4f);
            }
            a0 += nA * vA.x; a1 += nA * vA.y; a2 += nA * vA.z; a3 += nA * vA.w;
            b0 += nB * vB.x; b1 += nB * vB.y; b2 += nB * vB.z; b3 += nB * vB.w;
        }
    }
    if (e < s1) {
        int s = __ldg(&g_col[e]);
        float nr = __ldg(&g_dinv[s]) * di;
        if (act) {
            float4 v = __ldg((const float4*)(in + (size_t)s * FIN + c4));
            if (clip) {
                v.x = fminf(fmaxf(v.x, -0.4f), 0.4f);
                v.y = fminf(fmaxf(v.y, -0.4f), 0.4f);
                v.z = fminf(fmaxf(v.z, -0.4f), 0.4f);
                v.w = fminf(fmaxf(v.w, -0.4f), 0.4f);
            }
            a0 += nr * v.x; a1 += nr * v.y; a2 += nr * v.z; a3 += nr * v.w;
        }
    }
    if (act) {   // self loop
        float nn = di * di;
        float4 v = *(const float4*)(in + (size_t)gw * FIN + c4);
        if (clip) {
            v.x = fminf(fmaxf(v.x, -0.4f), 0.4f);
            v.y = fminf(fmaxf(v.y, -0.4f), 0.4f);
            v.z = fminf(fmaxf(v.z, -0.4f), 0.4f);
            v.w = fminf(fmaxf(v.w, -0.4f), 0.4f);
        }
        a0 += nn * v.x; a1 += nn * v.y; a2 += nn * v.z; a3 += nn * v.w;
    }
    a0 += b0; a1 += b1; a2 += b2; a3 += b3;
    uint2 ph = {0u, 0u}, pl = {0u, 0u};
    if (act) {
        ph.x = pack_hi(a0, a1); ph.y = pack_hi(a2, a3);
        pl.x = pack_lo(a0, a1); pl.y = pack_lo(a2, a3);
    }
    size_t o = ((size_t)gw * 128 + c4) >> 2;
    ((uint2*)oh)[o] = ph;
    ((uint2*)ol)[o] = pl;
}

// ------- weight prep ----------
__global__ void k_prep(const float* __restrict__ W, __nv_bfloat16* __restrict__ Th,
                       __nv_bfloat16* __restrict__ Tl, int K, int Nw, int Kpad, int Npad) {
    int idx = blockIdx.x * blockDim.x + threadIdx.x;
    if (idx >= Npad * Kpad) return;
    int n = idx / Kpad, k = idx % Kpad;
    float v = (k < K && n < Nw) ? W[(size_t)k * Nw + n] : 0.f;
    __nv_bfloat16 h = __float2bfloat16_rn(v);
    __nv_bfloat16 l = __float2bfloat16_rn(v - __bfloat162float(h));
    Th[idx] = h;
    Tl[idx] = l;
}

// ------- mma.sync bf16 split-precision GEMM, cp.async double-buffered -------
#define LDW 20                    // smem row stride in u32
#define CHB (128 * LDW * 4)       // bytes per array (10240)
#define BUFB (4 * CHB)            // bytes per buffer (40960)

__global__ void __launch_bounds__(256, 2)
k_mma(const __nv_bfloat16* __restrict__ Ah, const __nv_bfloat16* __restrict__ Al,
      const __nv_bfloat16* __restrict__ Bh, const __nv_bfloat16* __restrict__ Bl,
      const float* __restrict__ bias, float* __restrict__ C,
      __nv_bfloat16* __restrict__ Ch, __nv_bfloat16* __restrict__ Cl,
      int M, int Kpad, int Nc, int relu, int outmode) {
    extern __shared__ uint32_t sm[];
    uint32_t sbase = smem_u32(sm);

    int tid = threadIdx.x;
    int wid = tid >> 5, lane = tid & 31;
    int br = blockIdx.y * 128;
    int bc = blockIdx.x * 128;
    int wm = (wid & 3) * 32;
    int wn = (wid >> 2) * 64;

    // staging indices (2 uint4 per array per thread)
    int srow[2], sg[2];
    uint32_t soff[2];
    #pragma unroll
    for (int j = 0; j < 2; j++) {
        int idx = tid + (j << 8);
        srow[j] = idx >> 2; sg[j] = idx & 3;
        soff[j] = (uint32_t)(srow[j] * LDW + (sg[j] << 2)) * 4;
    }

    // ldmatrix offsets within an array
    uint32_t aOff[2], bOff[4];
    #pragma unroll
    for (int mt = 0; mt < 2; mt++)
        aOff[mt] = ((wm + mt * 16 + (lane & 15)) * 40 + ((lane >> 4) << 3)) * 2;
    #pragma unroll
    for (int ng = 0; ng < 4; ng++)
        bOff[ng] = ((wn + ng * 16 + (lane & 7) + ((lane >> 4) << 3)) * 40 + (((lane >> 3) & 1) << 3)) * 2;

    float acc[2][8][4];
    #pragma unroll
    for (int i = 0; i < 2; i++)
        #pragma unroll
        for (int j = 0; j < 8; j++)
            #pragma unroll
            for (int p = 0; p < 4; p++) acc[i][j][p] = 0.f;

    int nkc = Kpad >> 5;

    // stage chunk kc into buffer buf
    auto stage = [&](int kc, int buf) {
        int k0 = kc << 5;
        uint32_t b0 = sbase + buf * BUFB;
        #pragma unroll
        for (int j = 0; j < 2; j++) {
            int gm = br + srow[j];
            int ok = (gm < M);
            size_t ga = ((size_t)(ok ? gm : 0) * Kpad + k0) * 2 + (sg[j] << 4);
            int sz = ok ? 16 : 0;
            cp16z(b0 + soff[j], (const char*)Ah + ga, sz);
            cp16z(b0 + CHB + soff[j], (const char*)Al + ga, sz);
            size_t gb = ((size_t)(bc + srow[j]) * Kpad + k0) * 2 + (sg[j] << 4);
            cp16(b0 + 2 * CHB + soff[j], (const char*)Bh + gb);
            cp16(b0 + 3 * CHB + soff[j], (const char*)Bl + gb);
        }
    };

    stage(0, 0);
    CP_COMMIT();

    for (int kc = 0; kc < nkc; kc++) {
        int buf = kc & 1;
        if (kc + 1 < nkc) {
            stage(kc + 1, buf ^ 1);
            CP_COMMIT();
            CP_WAIT(1);
        } else {
            CP_WAIT(0);
        }
        __syncthreads();

        uint32_t aBaseH = sbase + buf * BUFB;
        uint32_t aBaseL = aBaseH + CHB;
        uint32_t bBaseH = aBaseH + 2 * CHB;
        uint32_t bBaseL = aBaseH + 3 * CHB;

        #pragma unroll
        for (int kk = 0; kk < 32; kk += 16) {
            uint32_t aH[2][4], aL[2][4], bb[8][2];
            #pragma unroll
            for (int mt = 0; mt < 2; mt++) ldsm4(aBaseH + aOff[mt] + kk * 2, aH[mt]);
            #pragma unroll
            for (int ng = 0; ng < 4; ng++) ldsm4(bBaseH + bOff[ng] + kk * 2, &bb[2 * ng][0]);
            #pragma unroll
            for (int mt = 0; mt < 2; mt++)
                #pragma unroll
                for (int nt = 0; nt < 8; nt++) mma16816(acc[mt][nt], aH[mt], bb[nt]);
            #pragma unroll
            for (int mt = 0; mt < 2; mt++) ldsm4(aBaseL + aOff[mt] + kk * 2, aL[mt]);
            #pragma unroll
            for (int mt = 0; mt < 2; mt++)
                #pragma unroll
                for (int nt = 0; nt < 8; nt++) mma16816(acc[mt][nt], aL[mt], bb[nt]);
            #pragma unroll
            for (int ng = 0; ng < 4; ng++) ldsm4(bBaseL + bOff[ng] + kk * 2, &bb[2 * ng][0]);
            #pragma unroll
            for (int mt = 0; mt < 2; mt++)
                #pragma unroll
                for (int nt = 0; nt < 8; nt++) mma16816(acc[mt][nt], aH[mt], bb[nt]);
        }
        __syncthreads();
    }

    // ---- epilogue ----
    #pragma unroll
    for (int mt = 0; mt < 2; mt++) {
        int r0 = br + wm + mt * 16 + (lane >> 2);
        #pragma unroll
        for (int nt = 0; nt < 8; nt++) {
            int gn = bc + wn + nt * 8 + ((lane & 3) << 1);
            float bv0 = (gn < Nc) ? bias[gn] : 0.f;
            float bv1 = (gn + 1 < Nc) ? bias[gn + 1] : 0.f;
            float c0 = acc[mt][nt][0] + bv0, c1 = acc[mt][nt][1] + bv1;
            float c2 = acc[mt][nt][2] + bv0, c3 = acc[mt][nt][3] + bv1;
            if (relu) {
                c0 = fmaxf(c0, 0.f); c1 = fmaxf(c1, 0.f);
                c2 = fmaxf(c2, 0.f); c3 = fmaxf(c3, 0.f);
            }
            if (outmode == 0) {
                if (gn + 1 < Nc) {
                    if (r0 < M) { float2 v = {c0, c1}; *(float2*)&C[(size_t)r0 * Nc + gn] = v; }
                    if (r0 + 8 < M) { float2 v = {c2, c3}; *(float2*)&C[(size_t)(r0 + 8) * Nc + gn] = v; }
                } else if (gn < Nc) {
                    if (r0 < M) C[(size_t)r0 * Nc + gn] = c0;
                    if (r0 + 8 < M) C[(size_t)(r0 + 8) * Nc + gn] = c2;
                }
            } else {
                if (gn + 1 < Nc) {
                    if (r0 < M) {
                        size_t o = ((size_t)r0 * Nc + gn) >> 1;
                        ((uint32_t*)Ch)[o] = pack_hi(c0, c1);
                        ((uint32_t*)Cl)[o] = pack_lo(c0, c1);
                    }
                    if (r0 + 8 < M) {
                        size_t o = ((size_t)(r0 + 8) * Nc + gn) >> 1;
                        ((uint32_t*)Ch)[o] = pack_hi(c2, c3);
                        ((uint32_t*)Cl)[o] = pack_lo(c2, c3);
                    }
                }
            }
        }
    }
}

// ---------------- BatchNorm statistics -----------------------
__global__ void k_bnstat(const float* __restrict__ z) {
    int col = threadIdx.x & 127;
    int half = threadIdx.x >> 7;
    float s = 0.f, s2 = 0.f;
    for (int r = blockIdx.x * 2 + half; r < NN; r += gridDim.x * 2) {
        float v = z[r * 128 + col];
        s += v; s2 += v * v;
    }
    __shared__ float sh[256], sh2[256];
    sh[threadIdx.x] = s; sh2[threadIdx.x] = s2;
    __syncthreads();
    if (threadIdx.x < 128) {
        atomicAdd(&g_bnsum[col], sh[threadIdx.x] + sh[threadIdx.x + 128]);
        atomicAdd(&g_bnsum[128 + col], sh2[threadIdx.x] + sh2[threadIdx.x + 128]);
    }
}
__global__ void k_bncoef(const float* __restrict__ gamma, const float* __restrict__ beta) {
    int c = threadIdx.x;
    float inv = 1.0f / (float)NN;
    float mu = g_bnsum[c] * inv;
    float var = g_bnsum[128 + c] * inv - mu * mu;
    float sc = gamma[c] * rsqrtf(var + 1e-5f);
    g_bncoef[c] = sc;
    g_bncoef[128 + c] = beta[c] - mu * sc;
}

// ------- final: BN affine + ReLU + [128x19] GEMV + log_softmax --------------
__global__ void k_final_out(const float* __restrict__ z, const float* __restrict__ W,
                            const float* __restrict__ b, float* __restrict__ out) {
    int gw = (blockIdx.x * blockDim.x + threadIdx.x) >> 5;
    if (gw >= NN) return;
    int lane = threadIdx.x & 31;
    float h[4];
    #pragma unroll
    for (int u = 0; u < 4; u++) {
        int c = lane + 32 * u;
        float v = z[gw * 128 + c];
        h[u] = fmaxf(v * g_bncoef[c] + g_bncoef[128 + c], 0.f);
    }
    float acc = (lane < 19) ? b[lane] : 0.f;
    #pragma unroll
    for (int u = 0; u < 4; u++) {
        #pragma unroll
        for (int l = 0; l < 32; l++) {
            float hb = __shfl_sync(0xffffffffu, h[u], l);
            if (lane < 19) acc += hb * __ldg(&W[(u * 32 + l) * 19 + lane]);
        }
    }
    float v = (lane < 19) ? acc : -3.4e38f;
    float m = v;
    #pragma unroll
    for (int off = 16; off > 0; off >>= 1) m = fmaxf(m, __shfl_xor_sync(0xffffffffu, m, off));
    float ex = (lane < 19) ? expf(v - m) : 0.f;
    float ssum = ex;
    #pragma unroll
    for (int off = 16; off > 0; off >>= 1) ssum += __shfl_xor_sync(0xffffffffu, ssum, off);
    if (lane < 19) out[gw * 19 + lane] = v - m - logf(ssum);
}

// ---------------------------------------------------------------------------
extern "C" void kernel_launch(void* const* d_in, const int* in_sizes, int n_in,
                              void* d_out, int out_size) {
    const float* x     = (const float*)d_in[0];
    const int*   ei    = (const int*)d_in[1];
    const float* W1    = (const float*)d_in[2];
    const float* b1    = (const float*)d_in[3];
    const float* W2    = (const float*)d_in[4];
    const float* b2    = (const float*)d_in[5];
    const float* W3    = (const float*)d_in[6];
    const float* b3    = (const float*)d_in[7];
    const float* fc1W  = (const float*)d_in[8];
    const float* fc1b  = (const float*)d_in[9];
    const float* fc2aW = (const float*)d_in[10];
    const float* fc2ab = (const float*)d_in[11];
    const float* gamma = (const float*)d_in[12];
    const float* beta  = (const float*)d_in[13];
    const float* fc2bW = (const float*)d_in[14];
    const float* fc2bb = (const float*)d_in[15];
    float* out = (float*)d_out;

    const int* src = ei;
    const int* dst = ei + EE;

    float* bufA;
    cudaGetSymbolAddress((void**)&bufA, g_bufA);
    __nv_bfloat16 *p0h, *p0l, *p1h, *p1l;
    cudaGetSymbolAddress((void**)&p0h, g_p0h);
    cudaGetSymbolAddress((void**)&p0l, g_p0l);
    cudaGetSymbolAddress((void**)&p1h, g_p1h);
    cudaGetSymbolAddress((void**)&p1l, g_p1l);
    __nv_bfloat16 *w1h, *w1l, *w2h, *w2l, *w3h, *w3l, *f1h, *f1l, *f2h, *f2l;
    cudaGetSymbolAddress((void**)&w1h, g_w1h);
    cudaGetSymbolAddress((void**)&w1l, g_w1l);
    cudaGetSymbolAddress((void**)&w2h, g_w2h);
    cudaGetSymbolAddress((void**)&w2l, g_w2l);
    cudaGetSymbolAddress((void**)&w3h, g_w3h);
    cudaGetSymbolAddress((void**)&w3l, g_w3l);
    cudaGetSymbolAddress((void**)&f1h, g_f1h);
    cudaGetSymbolAddress((void**)&f1l, g_f1l);
    cudaGetSymbolAddress((void**)&f2h, g_f2h);
    cudaGetSymbolAddress((void**)&f2l, g_f2l);

    cudaFuncSetAttribute(k_mma, cudaFuncAttributeMaxDynamicSharedMemorySize, 2 * BUFB);
    const size_t SMB = 2 * BUFB;   // 81920 bytes

    // CSR build
    k_zero<<<(NN + 255) / 256, 256>>>();
    k_count<<<(EE + 255) / 256, 256>>>(dst);
    k_scan1<<<(NN + 1023) / 1024, 1024>>>();
    k_scan2<<<1, 128>>>((NN + 1023) / 1024);
    k_rowptr<<<(NN + 255) / 256, 256>>>();
    k_fill<<<(EE + 255) / 256, 256>>>(src, dst);

    // weight prep
    k_prep<<<(128 * 128 + 255) / 256, 256>>>(W1, w1h, w1l, 100, 100, 128, 128);
    k_prep<<<(128 * 128 + 255) / 256, 256>>>(W2, w2h, w2l, 100, 100, 128, 128);
    k_prep<<<(256 * 128 + 255) / 256, 256>>>(W3, w3h, w3l, 100, 256, 128, 256);
    k_prep<<<(256 * 256 + 255) / 256, 256>>>(fc1W, f1h, f1l, 256, 256, 256, 256);
    k_prep<<<(128 * 256 + 255) / 256, 256>>>(fc2aW, f2h, f2l, 256, 128, 256, 128);

    const int aggBlocks = (NN * 32 + 255) / 256;
    const int gy = (NN + 127) / 128;  // 782

    // conv1
    k_aggb<<<aggBlocks, 256>>>(x, p0h, p0l, 1);
    k_mma<<<dim3(1, gy), 256, SMB>>>(p0h, p0l, w1h, w1l, b1, bufA, 0, 0, NN, 128, 100, 1, 0);
    // conv2
    k_aggb<<<aggBlocks, 256>>>(bufA, p0h, p0l, 0);
    k_mma<<<dim3(1, gy), 256, SMB>>>(p0h, p0l, w2h, w2l, b2, bufA, 0, 0, NN, 128, 100, 1, 0);
    // conv3 -> bf16 pair P1
    k_aggb<<<aggBlocks, 256>>>(bufA, p0h, p0l, 0);
    k_mma<<<dim3(2, gy), 256, SMB>>>(p0h, p0l, w3h, w3l, b3, 0, p1h, p1l, NN, 128, 256, 1, 1);
    // fc1 -> pair P0
    k_mma<<<dim3(2, gy), 256, SMB>>>(p1h, p1l, f1h, f1l, fc1b, 0, p0h, p0l, NN, 256, 256, 1, 1);
    // fc2a -> fp32 bufA
    k_mma<<<dim3(1, gy), 256, SMB>>>(p0h, p0l, f2h, f2l, fc2ab, bufA, 0, 0, NN, 256, 128, 0, 0);
    // BN + final
    k_bnstat<<<512, 256>>>(bufA);
    k_bncoef<<<1, 128>>>(gamma, beta);
    k_final_out<<<aggBlocks, 256>>>(bufA, fc2bW, fc2bb, out);
}